// round 11
// baseline (speedup 1.0000x reference)
#include <cuda_runtime.h>
#include <cuda_bf16.h>
#include <cuda_fp16.h>
#include <cstdint>

#define NMAX 100000
#define EMAX 1600000

// ---------------------------------------------------------------------------
// Device scratch (allocation-free rule)
// ---------------------------------------------------------------------------
__device__ int    g_deg [NMAX];
__device__ int    g_off [NMAX];
__device__ int    g_cur [NMAX];
__device__ int    g_ctr;
__device__ int    g_csr [EMAX];
__device__ float  g_dinv[NMAX];
__device__ __align__(16) __half g_h1 [(size_t)NMAX * 128];
__device__ __align__(16) __half g_h2 [(size_t)NMAX * 64];
__device__ __align__(16) uint32_t g_w1hi[8192], g_w1lo[8192];
__device__ __align__(16) uint32_t g_w2hi[4096], g_w2lo[4096];

// ---------------------------------------------------------------------------
// Helpers
// ---------------------------------------------------------------------------
__device__ __forceinline__ uint32_t smem_u32(const void* p) {
    uint32_t a;
    asm("{ .reg .u64 t; cvta.to.shared.u64 t, %1; cvt.u32.u64 %0, t; }" : "=r"(a) : "l"(p));
    return a;
}
__device__ __forceinline__ void ldsm_x4(uint32_t addr, uint32_t& r0, uint32_t& r1,
                                        uint32_t& r2, uint32_t& r3) {
    asm volatile("ldmatrix.sync.aligned.m8n8.x4.shared.b16 {%0,%1,%2,%3}, [%4];"
                 : "=r"(r0), "=r"(r1), "=r"(r2), "=r"(r3) : "r"(addr));
}
__device__ __forceinline__ void mma_bf16(float* c, const uint32_t* a, const uint32_t* b) {
    asm volatile("mma.sync.aligned.m16n8k16.row.col.f32.bf16.bf16.f32 "
                 "{%0,%1,%2,%3}, {%4,%5,%6,%7}, {%8,%9}, {%0,%1,%2,%3};"
                 : "+f"(c[0]), "+f"(c[1]), "+f"(c[2]), "+f"(c[3])
                 : "r"(a[0]), "r"(a[1]), "r"(a[2]), "r"(a[3]), "r"(b[0]), "r"(b[1]));
}
__device__ __forceinline__ uint32_t pack_bf16(float a, float b) {
    __nv_bfloat162 h = __floats2bfloat162_rn(a, b);
    return *(uint32_t*)&h;
}
__device__ __forceinline__ uint32_t f2_to_h2(float x, float y) {
    __half2 h = __floats2half2_rn(x, y);
    return *(uint32_t*)&h;
}
__device__ __forceinline__ float4 h4_to_f4(uint2 v) {
    float2 fa = __half22float2(*(__half2*)&v.x);
    float2 fb = __half22float2(*(__half2*)&v.y);
    return make_float4(fa.x, fa.y, fb.x, fb.y);
}

// ---------------------------------------------------------------------------
// CSR build: degree histogram -> warp-atomic offsets -> fill
// ---------------------------------------------------------------------------
__global__ void k_deg(const int* __restrict__ ei, int E) {
    int i = blockIdx.x * blockDim.x + threadIdx.x;
    if (i == 0) g_ctr = 0;                    // reset cursor for k_offsets
    if (i < E) atomicAdd(&g_deg[ei[E + i]], 1);
}

// Offsets via warp scan + one atomicAdd per warp (order-free CSR regions).
__global__ void k_offsets(int n) {
    int i = blockIdx.x * blockDim.x + threadIdx.x;
    int lane = threadIdx.x & 31;
    int deg = (i < n) ? g_deg[i] : 0;
    int x = deg;
    #pragma unroll
    for (int o = 1; o < 32; o <<= 1) {
        int y = __shfl_up_sync(0xffffffffu, x, o);
        if (lane >= o) x += y;
    }
    int excl = x - deg;
    int base = 0;
    if (lane == 31) base = atomicAdd(&g_ctr, x);
    base = __shfl_sync(0xffffffffu, base, 31);
    if (i < n) {
        int off = base + excl;
        g_off[i] = off;
        g_cur[i] = off;
        g_dinv[i] = rsqrtf((float)(deg + 1));
    }
}
__global__ void k_fill(const int* __restrict__ ei, int E) {
    int e = blockIdx.x * blockDim.x + threadIdx.x;
    if (e >= E) return;
    int s = ei[e];
    int d = ei[E + e];
    int p = atomicAdd(&g_cur[d], 1);
    g_csr[p] = s;
}

// ---------------------------------------------------------------------------
// Weight prep (fused, globals bound in device code)
// ---------------------------------------------------------------------------
__global__ void k_wprep_all(const float* __restrict__ W1, const float* __restrict__ W2) {
    int gi = blockIdx.x * blockDim.x + threadIdx.x;
    const float* W;
    uint32_t *bhi, *blo;
    int i, Nc;
    if (gi < 8192) {
        W = W1; bhi = g_w1hi; blo = g_w1lo; i = gi; Nc = 128;
    } else {
        gi -= 8192;
        if (gi >= 4096) return;
        W = W2; bhi = g_w2hi; blo = g_w2lo; i = gi; Nc = 64;
    }
    int nn = i >> 6;
    int k2 = i & 63;
    int k = k2 << 1;
    float v0 = W[k * Nc + nn];
    float v1 = W[(k + 1) * Nc + nn];
    __nv_bfloat16 h0 = __float2bfloat16(v0);
    __nv_bfloat16 h1 = __float2bfloat16(v1);
    uint32_t hi = (uint32_t)(*(uint16_t*)&h0) | ((uint32_t)(*(uint16_t*)&h1) << 16);
    uint32_t lo = pack_bf16(v0 - __bfloat162float(h0), v1 - __bfloat162float(h1));
    bhi[nn * 64 + k2] = hi;
    blo[nn * 64 + k2] = lo;
}

// ---------------------------------------------------------------------------
// conv1 GEMM (mma.sync bf16x3 + ldmatrix): g_h1(fp16) = dinv[row] * (x @ W1)
// 64-row tile, NCOL=128, warp grid 2m x 4n (MF=2, NF=4), STR=272 conflict-free.
// ---------------------------------------------------------------------------
__launch_bounds__(256, 1)
__global__ void k_tc_gemm1(const float* __restrict__ Aext, int n) {
    constexpr int TR  = 64;
    constexpr int NCOL = 128;
    constexpr int MF  = 2;
    constexpr int NF  = 4;
    constexpr int STR = 272;
    constexpr int A_HI = 0;
    constexpr int A_LO = TR * STR;           // 17408
    constexpr int B_HI = 2 * TR * STR;       // 34816
    constexpr int B_LO = B_HI + NCOL * STR;  // 69632

    extern __shared__ char smraw[];
    char* sm = smraw;
    const uint32_t smb = smem_u32(smraw);

    const int tid  = threadIdx.x;
    const int wid  = tid >> 5;
    const int lane = tid & 31;
    const int row0 = blockIdx.x * TR;

    // Stage W1 (padded rows)
    {
        const uint4* bh4 = (const uint4*)g_w1hi;
        const uint4* bl4 = (const uint4*)g_w1lo;
        #pragma unroll
        for (int i = tid; i < NCOL * 16; i += 256) {
            int r  = i >> 4;
            int kc = i & 15;
            *(uint4*)(sm + B_HI + r * STR + kc * 16) = bh4[i];
            *(uint4*)(sm + B_LO + r * STR + kc * 16) = bl4[i];
        }
    }

    // Load + split-convert x tile (64 x 128 fp32 -> bf16 hi/lo)
    #pragma unroll
    for (int i = tid; i < TR * 16; i += 256) {
        int r  = i >> 4;
        int kc = i & 15;
        int gr = row0 + r;
        float4 va = make_float4(0.f, 0.f, 0.f, 0.f);
        float4 vb = make_float4(0.f, 0.f, 0.f, 0.f);
        if (gr < n) {
            va = ((const float4*)Aext)[(size_t)gr * 32 + kc * 2];
            vb = ((const float4*)Aext)[(size_t)gr * 32 + kc * 2 + 1];
        }
        float f[8] = {va.x, va.y, va.z, va.w, vb.x, vb.y, vb.z, vb.w};
        uint4 hi, lo;
        uint32_t* hp = (uint32_t*)&hi;
        uint32_t* lp = (uint32_t*)&lo;
        #pragma unroll
        for (int j = 0; j < 4; j++) {
            __nv_bfloat162 h = __floats2bfloat162_rn(f[2 * j], f[2 * j + 1]);
            hp[j] = *(uint32_t*)&h;
            lp[j] = pack_bf16(f[2 * j]     - __bfloat162float(h.x),
                              f[2 * j + 1] - __bfloat162float(h.y));
        }
        *(uint4*)(sm + A_HI + r * STR + kc * 16) = hi;
        *(uint4*)(sm + A_LO + r * STR + kc * 16) = lo;
    }
    __syncthreads();

    const int wm   = wid % 2;
    const int wn   = wid / 2;
    const int mrow = wm * (MF * 16);
    const int ncol = wn * (NF * 8);
    const int lrow = lane & 7;
    const int sel  = lane >> 3;
    const int gr4  = lane >> 2;
    const int cl2  = (lane & 3) * 2;

    const int arow = mrow + lrow + ((sel & 1) << 3);
    const int akb  = (sel >> 1) << 4;
    const int brow = ncol + lrow + ((sel >> 1) << 3);
    const int bkb  = (sel & 1) << 4;

    float acc[MF][NF][4];
    #pragma unroll
    for (int mf = 0; mf < MF; mf++)
        #pragma unroll
        for (int nf = 0; nf < NF; nf++)
            #pragma unroll
            for (int j = 0; j < 4; j++) acc[mf][nf][j] = 0.f;

    #pragma unroll
    for (int ks = 0; ks < 8; ks++) {
        uint32_t ahi[MF][4], alo[MF][4];
        #pragma unroll
        for (int mf = 0; mf < MF; mf++) {
            uint32_t off = (uint32_t)((arow + mf * 16) * STR + ks * 32 + akb);
            ldsm_x4(smb + A_HI + off, ahi[mf][0], ahi[mf][1], ahi[mf][2], ahi[mf][3]);
            ldsm_x4(smb + A_LO + off, alo[mf][0], alo[mf][1], alo[mf][2], alo[mf][3]);
        }
        uint32_t bhi[NF][2], blo[NF][2];
        #pragma unroll
        for (int nf = 0; nf < NF; nf += 2) {
            uint32_t off = (uint32_t)((brow + nf * 8) * STR + ks * 32 + bkb);
            ldsm_x4(smb + B_HI + off, bhi[nf][0], bhi[nf][1], bhi[nf + 1][0], bhi[nf + 1][1]);
            ldsm_x4(smb + B_LO + off, blo[nf][0], blo[nf][1], blo[nf + 1][0], blo[nf + 1][1]);
        }
        #pragma unroll
        for (int mf = 0; mf < MF; mf++)
            #pragma unroll
            for (int nf = 0; nf < NF; nf++) {
                mma_bf16(acc[mf][nf], ahi[mf], bhi[nf]);
                mma_bf16(acc[mf][nf], ahi[mf], blo[nf]);
                mma_bf16(acc[mf][nf], alo[mf], bhi[nf]);
            }
    }

    #pragma unroll
    for (int mf = 0; mf < MF; mf++) {
        int r0g = row0 + mrow + mf * 16 + gr4;
        int r1g = r0g + 8;
        float dv0 = (r0g < n) ? g_dinv[r0g] : 0.f;
        float dv1 = (r1g < n) ? g_dinv[r1g] : 0.f;
        #pragma unroll
        for (int nf = 0; nf < NF; nf++) {
            int c = ncol + nf * 8 + cl2;
            if (r0g < n) {
                uint32_t p = f2_to_h2(acc[mf][nf][0] * dv0, acc[mf][nf][1] * dv0);
                *(uint32_t*)&g_h1[(size_t)r0g * NCOL + c] = p;
            }
            if (r1g < n) {
                uint32_t p = f2_to_h2(acc[mf][nf][2] * dv1, acc[mf][nf][3] * dv1);
                *(uint32_t*)&g_h1[(size_t)r1g * NCOL + c] = p;
            }
        }
    }
}

// ---------------------------------------------------------------------------
// FUSED gather1 + conv2 GEMM.
// Phase 1: warp w gathers nodes [w*8, w*8+8): a1 = relu(dinv*(h1[d]+sum h1[s])+b1),
//          split-converted straight into the SMEM A tile (bf16 hi/lo, fp32 source).
// Phase 2: NCOL=64 mma mainloop (warp grid 4m x 2n, MF=1, NF=4) -> g_h2 fp16.
// ---------------------------------------------------------------------------
__launch_bounds__(256, 1)
__global__ void k_gather_gemm2(const float* __restrict__ b1, int n) {
    constexpr int TR  = 64;
    constexpr int NCOL = 64;
    constexpr int MF  = 1;
    constexpr int NF  = 4;
    constexpr int STR = 272;
    constexpr int A_HI = 0;
    constexpr int A_LO = TR * STR;           // 17408
    constexpr int B_HI = 2 * TR * STR;       // 34816
    constexpr int B_LO = B_HI + NCOL * STR;  // 52224

    extern __shared__ char smraw[];
    char* sm = smraw;
    const uint32_t smb = smem_u32(smraw);

    const int tid  = threadIdx.x;
    const int wid  = tid >> 5;
    const int lane = tid & 31;
    const int row0 = blockIdx.x * TR;

    // Stage W2 (padded rows)
    {
        const uint4* bh4 = (const uint4*)g_w2hi;
        const uint4* bl4 = (const uint4*)g_w2lo;
        #pragma unroll
        for (int i = tid; i < NCOL * 16; i += 256) {
            int r  = i >> 4;
            int kc = i & 15;
            *(uint4*)(sm + B_HI + r * STR + kc * 16) = bh4[i];
            *(uint4*)(sm + B_LO + r * STR + kc * 16) = bl4[i];
        }
    }

    // Phase 1: gather + relu + split-convert into SMEM A tile.
    // Lane owns cols [4*lane, 4*lane+4) of each of this warp's 8 rows.
    const float4 bv = ((const float4*)b1)[lane];
    const uint2* H = (const uint2*)g_h1;
    #pragma unroll 1
    for (int r8 = 0; r8 < 8; r8++) {
        int r  = wid * 8 + r8;
        int gr = row0 + r;
        uint32_t hi0 = 0, hi1 = 0, lo0 = 0, lo1 = 0;
        if (gr < n) {
            int st = g_off[gr], cnt = g_deg[gr];
            float4 acc = h4_to_f4(H[(size_t)gr * 32 + lane]);   // self loop
            int j = 0;
            for (; j + 4 <= cnt; j += 4) {
                int s0 = g_csr[st + j], s1 = g_csr[st + j + 1];
                int s2 = g_csr[st + j + 2], s3 = g_csr[st + j + 3];
                float4 v0 = h4_to_f4(H[(size_t)s0 * 32 + lane]);
                float4 v1 = h4_to_f4(H[(size_t)s1 * 32 + lane]);
                float4 v2 = h4_to_f4(H[(size_t)s2 * 32 + lane]);
                float4 v3 = h4_to_f4(H[(size_t)s3 * 32 + lane]);
                acc.x += (v0.x + v1.x) + (v2.x + v3.x);
                acc.y += (v0.y + v1.y) + (v2.y + v3.y);
                acc.z += (v0.z + v1.z) + (v2.z + v3.z);
                acc.w += (v0.w + v1.w) + (v2.w + v3.w);
            }
            for (; j < cnt; j++) {
                int s = g_csr[st + j];
                float4 v = h4_to_f4(H[(size_t)s * 32 + lane]);
                acc.x += v.x; acc.y += v.y; acc.z += v.z; acc.w += v.w;
            }
            float dv = g_dinv[gr];
            float ox = fmaxf(fmaf(acc.x, dv, bv.x), 0.f);
            float oy = fmaxf(fmaf(acc.y, dv, bv.y), 0.f);
            float oz = fmaxf(fmaf(acc.z, dv, bv.z), 0.f);
            float ow = fmaxf(fmaf(acc.w, dv, bv.w), 0.f);
            __nv_bfloat162 h01 = __floats2bfloat162_rn(ox, oy);
            __nv_bfloat162 h23 = __floats2bfloat162_rn(oz, ow);
            hi0 = *(uint32_t*)&h01;
            hi1 = *(uint32_t*)&h23;
            lo0 = pack_bf16(ox - __bfloat162float(h01.x), oy - __bfloat162float(h01.y));
            lo1 = pack_bf16(oz - __bfloat162float(h23.x), ow - __bfloat162float(h23.y));
        }
        int ro = r * STR + 8 * lane;
        *(uint32_t*)(sm + A_HI + ro)     = hi0;
        *(uint32_t*)(sm + A_HI + ro + 4) = hi1;
        *(uint32_t*)(sm + A_LO + ro)     = lo0;
        *(uint32_t*)(sm + A_LO + ro + 4) = lo1;
    }
    __syncthreads();

    // Phase 2: mma mainloop (NCOL=64: warp grid 4m x 2n)
    const int wm   = wid % 4;
    const int wn   = wid / 4;
    const int mrow = wm * 16;
    const int ncol = wn * (NF * 8);
    const int lrow = lane & 7;
    const int sel  = lane >> 3;
    const int gr4  = lane >> 2;
    const int cl2  = (lane & 3) * 2;

    const int arow = mrow + lrow + ((sel & 1) << 3);
    const int akb  = (sel >> 1) << 4;
    const int brow = ncol + lrow + ((sel >> 1) << 3);
    const int bkb  = (sel & 1) << 4;

    float acc[NF][4];
    #pragma unroll
    for (int nf = 0; nf < NF; nf++)
        #pragma unroll
        for (int j = 0; j < 4; j++) acc[nf][j] = 0.f;

    #pragma unroll
    for (int ks = 0; ks < 8; ks++) {
        uint32_t ahi[4], alo[4];
        uint32_t off = (uint32_t)(arow * STR + ks * 32 + akb);
        ldsm_x4(smb + A_HI + off, ahi[0], ahi[1], ahi[2], ahi[3]);
        ldsm_x4(smb + A_LO + off, alo[0], alo[1], alo[2], alo[3]);
        uint32_t bhi[NF][2], blo[NF][2];
        #pragma unroll
        for (int nf = 0; nf < NF; nf += 2) {
            uint32_t boff = (uint32_t)((brow + nf * 8) * STR + ks * 32 + bkb);
            ldsm_x4(smb + B_HI + boff, bhi[nf][0], bhi[nf][1], bhi[nf + 1][0], bhi[nf + 1][1]);
            ldsm_x4(smb + B_LO + boff, blo[nf][0], blo[nf][1], blo[nf + 1][0], blo[nf + 1][1]);
        }
        #pragma unroll
        for (int nf = 0; nf < NF; nf++) {
            mma_bf16(acc[nf], ahi, bhi[nf]);
            mma_bf16(acc[nf], ahi, blo[nf]);
            mma_bf16(acc[nf], alo, bhi[nf]);
        }
    }

    // Epilogue: h2 = dinv[row] * acc (fp16)
    {
        int r0g = row0 + mrow + gr4;
        int r1g = r0g + 8;
        float dv0 = (r0g < n) ? g_dinv[r0g] : 0.f;
        float dv1 = (r1g < n) ? g_dinv[r1g] : 0.f;
        #pragma unroll
        for (int nf = 0; nf < NF; nf++) {
            int c = ncol + nf * 8 + cl2;
            if (r0g < n) {
                uint32_t p = f2_to_h2(acc[nf][0] * dv0, acc[nf][1] * dv0);
                *(uint32_t*)&g_h2[(size_t)r0g * NCOL + c] = p;
            }
            if (r1g < n) {
                uint32_t p = f2_to_h2(acc[nf][2] * dv1, acc[nf][3] * dv1);
                *(uint32_t*)&g_h2[(size_t)r1g * NCOL + c] = p;
            }
        }
    }
}

// ---------------------------------------------------------------------------
// gather2: out(fp32) = dinv[d]*(h2[d] + sum h2[s]) + b2
// ---------------------------------------------------------------------------
__global__ void k_gather2(float* __restrict__ out, const float* __restrict__ b2, int n) {
    int t = blockIdx.x * blockDim.x + threadIdx.x;
    int ch = t & 15;
    int g = t >> 4;
    if (g >= n) return;
    int st = g_off[g], cnt = g_deg[g];
    const uint2* H = (const uint2*)g_h2;
    float4 acc = h4_to_f4(H[(size_t)g * 16 + ch]);
    int j = 0;
    for (; j + 4 <= cnt; j += 4) {
        int s0 = g_csr[st + j], s1 = g_csr[st + j + 1];
        int s2 = g_csr[st + j + 2], s3 = g_csr[st + j + 3];
        float4 v0 = h4_to_f4(H[(size_t)s0 * 16 + ch]);
        float4 v1 = h4_to_f4(H[(size_t)s1 * 16 + ch]);
        float4 v2 = h4_to_f4(H[(size_t)s2 * 16 + ch]);
        float4 v3 = h4_to_f4(H[(size_t)s3 * 16 + ch]);
        acc.x += (v0.x + v1.x) + (v2.x + v3.x);
        acc.y += (v0.y + v1.y) + (v2.y + v3.y);
        acc.z += (v0.z + v1.z) + (v2.z + v3.z);
        acc.w += (v0.w + v1.w) + (v2.w + v3.w);
    }
    for (; j < cnt; j++) {
        int s = g_csr[st + j];
        float4 v = h4_to_f4(H[(size_t)s * 16 + ch]);
        acc.x += v.x; acc.y += v.y; acc.z += v.z; acc.w += v.w;
    }
    float dv = g_dinv[g];
    float4 b = ((const float4*)b2)[ch];
    acc.x = fmaf(acc.x, dv, b.x);
    acc.y = fmaf(acc.y, dv, b.y);
    acc.z = fmaf(acc.z, dv, b.z);
    acc.w = fmaf(acc.w, dv, b.w);
    ((float4*)out)[(size_t)g * 16 + ch] = acc;
}

// ---------------------------------------------------------------------------
// Launch
// ---------------------------------------------------------------------------
extern "C" void kernel_launch(void* const* d_in, const int* in_sizes, int n_in,
                              void* d_out, int out_size) {
    const float* x  = (const float*)d_in[0];
    const int*   ei = (const int*)  d_in[1];
    const float* W1 = (const float*)d_in[2];
    const float* b1 = (const float*)d_in[3];
    const float* W2 = (const float*)d_in[4];
    const float* b2 = (const float*)d_in[5];
    float* out = (float*)d_out;

    const int n = in_sizes[0] / 128;
    const int E = in_sizes[1] / 2;

    const int smem1 = 2 * 64 * 272 + 2 * 128 * 272;  // 104448
    const int smem2 = 2 * 64 * 272 + 2 * 64  * 272;  //  69632
    cudaFuncSetAttribute(k_tc_gemm1,      cudaFuncAttributeMaxDynamicSharedMemorySize, smem1);
    cudaFuncSetAttribute(k_gather_gemm2,  cudaFuncAttributeMaxDynamicSharedMemorySize, smem2);

    // Weight prep
    k_wprep_all<<<48, 256>>>(W1, W2);

    // CSR build + normalization (scan chain replaced by warp-atomic offsets)
    int* degp = nullptr;
    cudaGetSymbolAddress((void**)&degp, g_deg);
    cudaMemsetAsync(degp, 0, n * sizeof(int), 0);
    k_deg<<<(E + 255) / 256, 256>>>(ei, E);
    k_offsets<<<(n + 255) / 256, 256>>>(n);
    k_fill<<<(E + 255) / 256, 256>>>(ei, E);

    const int gg = (n + 63) / 64;

    // conv1 GEMM
    k_tc_gemm1<<<gg, 256, smem1>>>(x, n);

    // fused gather1 + conv2 GEMM
    k_gather_gemm2<<<gg, 256, smem2>>>(b1, n);

    // conv2 aggregation
    k_gather2<<<(n * 16 + 255) / 256, 256>>>(out, b2, n);
}

// round 12
// speedup vs baseline: 1.0996x; 1.0996x over previous
#include <cuda_runtime.h>
#include <cuda_bf16.h>
#include <cuda_fp16.h>
#include <cstdint>

#define NMAX 100000
#define EMAX 1600000

// ---------------------------------------------------------------------------
// Device scratch (allocation-free rule)
// ---------------------------------------------------------------------------
__device__ int    g_deg [NMAX];
__device__ int    g_off [NMAX];
__device__ int    g_cur [NMAX];
__device__ int    g_ctr;
__device__ int    g_csr [EMAX];
__device__ float  g_dinv[NMAX];
__device__ __align__(16) __half g_h1 [(size_t)NMAX * 128];
__device__ __align__(16) __half g_a1 [(size_t)NMAX * 128];
__device__ __align__(16) __half g_h2 [(size_t)NMAX * 64];
__device__ __align__(16) uint32_t g_w1hi[8192], g_w1lo[8192];
__device__ __align__(16) uint32_t g_w2hi[4096], g_w2lo[4096];

// ---------------------------------------------------------------------------
// Helpers
// ---------------------------------------------------------------------------
__device__ __forceinline__ uint32_t smem_u32(const void* p) {
    uint32_t a;
    asm("{ .reg .u64 t; cvta.to.shared.u64 t, %1; cvt.u32.u64 %0, t; }" : "=r"(a) : "l"(p));
    return a;
}
__device__ __forceinline__ void ldsm_x4(uint32_t addr, uint32_t& r0, uint32_t& r1,
                                        uint32_t& r2, uint32_t& r3) {
    asm volatile("ldmatrix.sync.aligned.m8n8.x4.shared.b16 {%0,%1,%2,%3}, [%4];"
                 : "=r"(r0), "=r"(r1), "=r"(r2), "=r"(r3) : "r"(addr));
}
__device__ __forceinline__ void mma_bf16(float* c, const uint32_t* a, const uint32_t* b) {
    asm volatile("mma.sync.aligned.m16n8k16.row.col.f32.bf16.bf16.f32 "
                 "{%0,%1,%2,%3}, {%4,%5,%6,%7}, {%8,%9}, {%0,%1,%2,%3};"
                 : "+f"(c[0]), "+f"(c[1]), "+f"(c[2]), "+f"(c[3])
                 : "r"(a[0]), "r"(a[1]), "r"(a[2]), "r"(a[3]), "r"(b[0]), "r"(b[1]));
}
__device__ __forceinline__ uint32_t pack_bf16(float a, float b) {
    __nv_bfloat162 h = __floats2bfloat162_rn(a, b);
    return *(uint32_t*)&h;
}
__device__ __forceinline__ uint32_t f2_to_h2(float x, float y) {
    __half2 h = __floats2half2_rn(x, y);
    return *(uint32_t*)&h;
}
__device__ __forceinline__ float4 h4_to_f4(uint2 v) {
    float2 fa = __half22float2(*(__half2*)&v.x);
    float2 fb = __half22float2(*(__half2*)&v.y);
    return make_float4(fa.x, fa.y, fb.x, fb.y);
}

// ---------------------------------------------------------------------------
// CSR build: degree histogram (4 edges/thread) -> warp-atomic offsets ->
// fill (4 edges/thread). MLP=4 on the atomic path.
// ---------------------------------------------------------------------------
__global__ void k_deg(const int* __restrict__ ei, int E) {
    int t = blockIdx.x * blockDim.x + threadIdx.x;
    if (t == 0) g_ctr = 0;
    int e0 = t * 4;
    if (e0 + 4 <= E) {
        int4 d = *(const int4*)(ei + E + e0);
        atomicAdd(&g_deg[d.x], 1);
        atomicAdd(&g_deg[d.y], 1);
        atomicAdd(&g_deg[d.z], 1);
        atomicAdd(&g_deg[d.w], 1);
    } else {
        for (int e = e0; e < E; e++) atomicAdd(&g_deg[ei[E + e]], 1);
    }
}

// Offsets via warp scan + one atomicAdd per warp (order-free CSR regions).
__global__ void k_offsets(int n) {
    int i = blockIdx.x * blockDim.x + threadIdx.x;
    int lane = threadIdx.x & 31;
    int deg = (i < n) ? g_deg[i] : 0;
    int x = deg;
    #pragma unroll
    for (int o = 1; o < 32; o <<= 1) {
        int y = __shfl_up_sync(0xffffffffu, x, o);
        if (lane >= o) x += y;
    }
    int excl = x - deg;
    int base = 0;
    if (lane == 31) base = atomicAdd(&g_ctr, x);
    base = __shfl_sync(0xffffffffu, base, 31);
    if (i < n) {
        int off = base + excl;
        g_off[i] = off;
        g_cur[i] = off;
        g_dinv[i] = rsqrtf((float)(deg + 1));
    }
}

__global__ void k_fill(const int* __restrict__ ei, int E) {
    int t = blockIdx.x * blockDim.x + threadIdx.x;
    int e0 = t * 4;
    if (e0 + 4 <= E) {
        int4 s = *(const int4*)(ei + e0);
        int4 d = *(const int4*)(ei + E + e0);
        int p0 = atomicAdd(&g_cur[d.x], 1);
        int p1 = atomicAdd(&g_cur[d.y], 1);
        int p2 = atomicAdd(&g_cur[d.z], 1);
        int p3 = atomicAdd(&g_cur[d.w], 1);
        g_csr[p0] = s.x;
        g_csr[p1] = s.y;
        g_csr[p2] = s.z;
        g_csr[p3] = s.w;
    } else {
        for (int e = e0; e < E; e++) {
            int p = atomicAdd(&g_cur[ei[E + e]], 1);
            g_csr[p] = ei[e];
        }
    }
}

// ---------------------------------------------------------------------------
// Weight prep (fused, globals bound in device code)
// ---------------------------------------------------------------------------
__global__ void k_wprep_all(const float* __restrict__ W1, const float* __restrict__ W2) {
    int gi = blockIdx.x * blockDim.x + threadIdx.x;
    const float* W;
    uint32_t *bhi, *blo;
    int i, Nc;
    if (gi < 8192) {
        W = W1; bhi = g_w1hi; blo = g_w1lo; i = gi; Nc = 128;
    } else {
        gi -= 8192;
        if (gi >= 4096) return;
        W = W2; bhi = g_w2hi; blo = g_w2lo; i = gi; Nc = 64;
    }
    int nn = i >> 6;
    int k2 = i & 63;
    int k = k2 << 1;
    float v0 = W[k * Nc + nn];
    float v1 = W[(k + 1) * Nc + nn];
    __nv_bfloat16 h0 = __float2bfloat16(v0);
    __nv_bfloat16 h1 = __float2bfloat16(v1);
    uint32_t hi = (uint32_t)(*(uint16_t*)&h0) | ((uint32_t)(*(uint16_t*)&h1) << 16);
    uint32_t lo = pack_bf16(v0 - __bfloat162float(h0), v1 - __bfloat162float(h1));
    bhi[nn * 64 + k2] = hi;
    blo[nn * 64 + k2] = lo;
}

// ---------------------------------------------------------------------------
// Tensor-core GEMM via mma.sync bf16x3 + ldmatrix (R10 proven version)
// MODE 1: A = x (fp32 ext) -> g_h1.  MODE 2: A = g_a1 (fp16) -> g_h2.
// ---------------------------------------------------------------------------
template <int NCOL, int MODE>
__launch_bounds__(256, 1)
__global__ void k_tc_gemm(const float* __restrict__ Aext, int n) {
    constexpr int TR  = 64;
    constexpr int NWM = (NCOL == 128) ? 2 : 4;
    constexpr int MF  = TR / (NWM * 16);
    constexpr int NWN = 8 / NWM;
    constexpr int NF  = NCOL / (NWN * 8);
    constexpr int STR = 272;
    constexpr int A_HI = 0;
    constexpr int A_LO = TR * STR;
    constexpr int B_HI = 2 * TR * STR;
    constexpr int B_LO = B_HI + NCOL * STR;

    extern __shared__ char smraw[];
    char* sm = smraw;
    const uint32_t smb = smem_u32(smraw);

    const int tid  = threadIdx.x;
    const int wid  = tid >> 5;
    const int lane = tid & 31;
    const int row0 = blockIdx.x * TR;

    __half* Od = (MODE == 1) ? g_h1 : g_h2;
    const uint32_t* Bhig = (MODE == 1) ? g_w1hi : g_w2hi;
    const uint32_t* Blog = (MODE == 1) ? g_w1lo : g_w2lo;

    {
        const uint4* bh4 = (const uint4*)Bhig;
        const uint4* bl4 = (const uint4*)Blog;
        constexpr int NB4 = NCOL * 16;
        #pragma unroll
        for (int i = tid; i < NB4; i += 256) {
            int r  = i >> 4;
            int kc = i & 15;
            *(uint4*)(sm + B_HI + r * STR + kc * 16) = bh4[i];
            *(uint4*)(sm + B_LO + r * STR + kc * 16) = bl4[i];
        }
    }

    #pragma unroll
    for (int i = tid; i < TR * 16; i += 256) {
        int r  = i >> 4;
        int kc = i & 15;
        int gr = row0 + r;
        float f[8];
        if (MODE == 1) {
            float4 va = make_float4(0.f, 0.f, 0.f, 0.f);
            float4 vb = make_float4(0.f, 0.f, 0.f, 0.f);
            if (gr < n) {
                va = ((const float4*)Aext)[(size_t)gr * 32 + kc * 2];
                vb = ((const float4*)Aext)[(size_t)gr * 32 + kc * 2 + 1];
            }
            f[0] = va.x; f[1] = va.y; f[2] = va.z; f[3] = va.w;
            f[4] = vb.x; f[5] = vb.y; f[6] = vb.z; f[7] = vb.w;
        } else {
            uint4 v = make_uint4(0u, 0u, 0u, 0u);
            if (gr < n) v = ((const uint4*)g_a1)[(size_t)gr * 16 + kc];
            float2 f0 = __half22float2(*(__half2*)&v.x);
            float2 f1 = __half22float2(*(__half2*)&v.y);
            float2 f2 = __half22float2(*(__half2*)&v.z);
            float2 f3 = __half22float2(*(__half2*)&v.w);
            f[0] = f0.x; f[1] = f0.y; f[2] = f1.x; f[3] = f1.y;
            f[4] = f2.x; f[5] = f2.y; f[6] = f3.x; f[7] = f3.y;
        }
        uint4 hi, lo;
        uint32_t* hp = (uint32_t*)&hi;
        uint32_t* lp = (uint32_t*)&lo;
        #pragma unroll
        for (int j = 0; j < 4; j++) {
            __nv_bfloat162 h = __floats2bfloat162_rn(f[2 * j], f[2 * j + 1]);
            hp[j] = *(uint32_t*)&h;
            lp[j] = pack_bf16(f[2 * j]     - __bfloat162float(h.x),
                              f[2 * j + 1] - __bfloat162float(h.y));
        }
        *(uint4*)(sm + A_HI + r * STR + kc * 16) = hi;
        *(uint4*)(sm + A_LO + r * STR + kc * 16) = lo;
    }
    __syncthreads();

    const int wm   = wid % NWM;
    const int wn   = wid / NWM;
    const int mrow = wm * (MF * 16);
    const int ncol = wn * (NF * 8);
    const int lrow = lane & 7;
    const int sel  = lane >> 3;
    const int gr4  = lane >> 2;
    const int cl2  = (lane & 3) * 2;

    const int arow = mrow + lrow + ((sel & 1) << 3);
    const int akb  = (sel >> 1) << 4;
    const int brow = ncol + lrow + ((sel >> 1) << 3);
    const int bkb  = (sel & 1) << 4;

    float acc[MF][NF][4];
    #pragma unroll
    for (int mf = 0; mf < MF; mf++)
        #pragma unroll
        for (int nf = 0; nf < NF; nf++)
            #pragma unroll
            for (int j = 0; j < 4; j++) acc[mf][nf][j] = 0.f;

    #pragma unroll
    for (int ks = 0; ks < 8; ks++) {
        uint32_t ahi[MF][4], alo[MF][4];
        #pragma unroll
        for (int mf = 0; mf < MF; mf++) {
            uint32_t off = (uint32_t)((arow + mf * 16) * STR + ks * 32 + akb);
            ldsm_x4(smb + A_HI + off, ahi[mf][0], ahi[mf][1], ahi[mf][2], ahi[mf][3]);
            ldsm_x4(smb + A_LO + off, alo[mf][0], alo[mf][1], alo[mf][2], alo[mf][3]);
        }
        uint32_t bhi[NF][2], blo[NF][2];
        #pragma unroll
        for (int nf = 0; nf < NF; nf += 2) {
            uint32_t off = (uint32_t)((brow + nf * 8) * STR + ks * 32 + bkb);
            ldsm_x4(smb + B_HI + off, bhi[nf][0], bhi[nf][1], bhi[nf + 1][0], bhi[nf + 1][1]);
            ldsm_x4(smb + B_LO + off, blo[nf][0], blo[nf][1], blo[nf + 1][0], blo[nf + 1][1]);
        }
        #pragma unroll
        for (int mf = 0; mf < MF; mf++)
            #pragma unroll
            for (int nf = 0; nf < NF; nf++) {
                mma_bf16(acc[mf][nf], ahi[mf], bhi[nf]);
                mma_bf16(acc[mf][nf], ahi[mf], blo[nf]);
                mma_bf16(acc[mf][nf], alo[mf], bhi[nf]);
            }
    }

    #pragma unroll
    for (int mf = 0; mf < MF; mf++) {
        int r0g = row0 + mrow + mf * 16 + gr4;
        int r1g = r0g + 8;
        float dv0 = (r0g < n) ? g_dinv[r0g] : 0.f;
        float dv1 = (r1g < n) ? g_dinv[r1g] : 0.f;
        #pragma unroll
        for (int nf = 0; nf < NF; nf++) {
            int c = ncol + nf * 8 + cl2;
            if (r0g < n) {
                uint32_t p = f2_to_h2(acc[mf][nf][0] * dv0, acc[mf][nf][1] * dv0);
                *(uint32_t*)&Od[(size_t)r0g * NCOL + c] = p;
            }
            if (r1g < n) {
                uint32_t p = f2_to_h2(acc[mf][nf][2] * dv1, acc[mf][nf][3] * dv1);
                *(uint32_t*)&Od[(size_t)r1g * NCOL + c] = p;
            }
        }
    }
}

// ---------------------------------------------------------------------------
// Gather aggregation (CSR, no atomics), fp16 reads, fp32 accumulate (R8 form)
// ---------------------------------------------------------------------------
__global__ void k_gather1(const float* __restrict__ b1, int n) {
    int t = blockIdx.x * blockDim.x + threadIdx.x;
    int lane = t & 31;
    int w = t >> 5;
    if (w >= n) return;
    int st = g_off[w], cnt = g_deg[w];
    const uint2* H = (const uint2*)g_h1;
    float4 acc = h4_to_f4(H[(size_t)w * 32 + lane]);
    int j = 0;
    for (; j + 4 <= cnt; j += 4) {
        int s0 = g_csr[st + j], s1 = g_csr[st + j + 1];
        int s2 = g_csr[st + j + 2], s3 = g_csr[st + j + 3];
        float4 v0 = h4_to_f4(H[(size_t)s0 * 32 + lane]);
        float4 v1 = h4_to_f4(H[(size_t)s1 * 32 + lane]);
        float4 v2 = h4_to_f4(H[(size_t)s2 * 32 + lane]);
        float4 v3 = h4_to_f4(H[(size_t)s3 * 32 + lane]);
        acc.x += (v0.x + v1.x) + (v2.x + v3.x);
        acc.y += (v0.y + v1.y) + (v2.y + v3.y);
        acc.z += (v0.z + v1.z) + (v2.z + v3.z);
        acc.w += (v0.w + v1.w) + (v2.w + v3.w);
    }
    for (; j < cnt; j++) {
        int s = g_csr[st + j];
        float4 v = h4_to_f4(H[(size_t)s * 32 + lane]);
        acc.x += v.x; acc.y += v.y; acc.z += v.z; acc.w += v.w;
    }
    float dv = g_dinv[w];
    float4 b = ((const float4*)b1)[lane];
    float ox = fmaxf(fmaf(acc.x, dv, b.x), 0.f);
    float oy = fmaxf(fmaf(acc.y, dv, b.y), 0.f);
    float oz = fmaxf(fmaf(acc.z, dv, b.z), 0.f);
    float ow = fmaxf(fmaf(acc.w, dv, b.w), 0.f);
    uint2 o;
    o.x = f2_to_h2(ox, oy);
    o.y = f2_to_h2(oz, ow);
    ((uint2*)g_a1)[(size_t)w * 32 + lane] = o;
}

__global__ void k_gather2(float* __restrict__ out, const float* __restrict__ b2, int n) {
    int t = blockIdx.x * blockDim.x + threadIdx.x;
    int ch = t & 15;
    int g = t >> 4;
    if (g >= n) return;
    int st = g_off[g], cnt = g_deg[g];
    const uint2* H = (const uint2*)g_h2;
    float4 acc = h4_to_f4(H[(size_t)g * 16 + ch]);
    int j = 0;
    for (; j + 4 <= cnt; j += 4) {
        int s0 = g_csr[st + j], s1 = g_csr[st + j + 1];
        int s2 = g_csr[st + j + 2], s3 = g_csr[st + j + 3];
        float4 v0 = h4_to_f4(H[(size_t)s0 * 16 + ch]);
        float4 v1 = h4_to_f4(H[(size_t)s1 * 16 + ch]);
        float4 v2 = h4_to_f4(H[(size_t)s2 * 16 + ch]);
        float4 v3 = h4_to_f4(H[(size_t)s3 * 16 + ch]);
        acc.x += (v0.x + v1.x) + (v2.x + v3.x);
        acc.y += (v0.y + v1.y) + (v2.y + v3.y);
        acc.z += (v0.z + v1.z) + (v2.z + v3.z);
        acc.w += (v0.w + v1.w) + (v2.w + v3.w);
    }
    for (; j < cnt; j++) {
        int s = g_csr[st + j];
        float4 v = h4_to_f4(H[(size_t)s * 16 + ch]);
        acc.x += v.x; acc.y += v.y; acc.z += v.z; acc.w += v.w;
    }
    float dv = g_dinv[g];
    float4 b = ((const float4*)b2)[ch];
    acc.x = fmaf(acc.x, dv, b.x);
    acc.y = fmaf(acc.y, dv, b.y);
    acc.z = fmaf(acc.z, dv, b.z);
    acc.w = fmaf(acc.w, dv, b.w);
    ((float4*)out)[(size_t)g * 16 + ch] = acc;
}

// ---------------------------------------------------------------------------
// Launch (R10 structure + k_offsets + vectorized k_deg/k_fill)
// ---------------------------------------------------------------------------
extern "C" void kernel_launch(void* const* d_in, const int* in_sizes, int n_in,
                              void* d_out, int out_size) {
    const float* x  = (const float*)d_in[0];
    const int*   ei = (const int*)  d_in[1];
    const float* W1 = (const float*)d_in[2];
    const float* b1 = (const float*)d_in[3];
    const float* W2 = (const float*)d_in[4];
    const float* b2 = (const float*)d_in[5];
    float* out = (float*)d_out;

    const int n = in_sizes[0] / 128;
    const int E = in_sizes[1] / 2;
    const int e4 = (E + 3) / 4;

    const int smem1 = 2 * 64 * 272 + 2 * 128 * 272;  // 104448
    const int smem2 = 2 * 64 * 272 + 2 * 64  * 272;  //  69632
    cudaFuncSetAttribute(k_tc_gemm<128, 1>, cudaFuncAttributeMaxDynamicSharedMemorySize, smem1);
    cudaFuncSetAttribute(k_tc_gemm<64,  2>, cudaFuncAttributeMaxDynamicSharedMemorySize, smem2);

    // Weight prep
    k_wprep_all<<<48, 256>>>(W1, W2);

    // CSR build + normalization
    int* degp = nullptr;
    cudaGetSymbolAddress((void**)&degp, g_deg);
    cudaMemsetAsync(degp, 0, n * sizeof(int), 0);
    k_deg<<<(e4 + 255) / 256, 256>>>(ei, E);
    k_offsets<<<(n + 255) / 256, 256>>>(n);
    k_fill<<<(e4 + 255) / 256, 256>>>(ei, E);

    const int gg = (n + 63) / 64;

    // conv1
    k_tc_gemm<128, 1><<<gg, 256, smem1>>>(x, n);
    k_gather1<<<(n * 32 + 255) / 256, 256>>>(b1, n);

    // conv2
    k_tc_gemm<64, 2><<<gg, 256, smem2>>>(nullptr, n);
    k_gather2<<<(n * 16 + 255) / 256, 256>>>(out, b2, n);
}

// round 13
// speedup vs baseline: 1.1181x; 1.0169x over previous
#include <cuda_runtime.h>
#include <cuda_bf16.h>
#include <cuda_fp16.h>
#include <cstdint>

#define NMAX 100000
#define EMAX 1600000

// ---------------------------------------------------------------------------
// Device scratch (allocation-free rule)
// ---------------------------------------------------------------------------
__device__ int    g_deg [NMAX];
__device__ int    g_off [NMAX];
__device__ int    g_cur [NMAX];
__device__ int    g_ctr;
__device__ int    g_csr [EMAX];
__device__ float  g_dinv[NMAX];
__device__ __align__(16) __half g_h1 [(size_t)NMAX * 128];
__device__ __align__(16) __half g_a1 [(size_t)NMAX * 128];
__device__ __align__(16) __half g_h2 [(size_t)NMAX * 64];
__device__ __align__(16) uint32_t g_w1hi[8192], g_w1lo[8192];
__device__ __align__(16) uint32_t g_w2hi[4096], g_w2lo[4096];

// ---------------------------------------------------------------------------
// Helpers
// ---------------------------------------------------------------------------
__device__ __forceinline__ uint32_t smem_u32(const void* p) {
    uint32_t a;
    asm("{ .reg .u64 t; cvta.to.shared.u64 t, %1; cvt.u32.u64 %0, t; }" : "=r"(a) : "l"(p));
    return a;
}
__device__ __forceinline__ void ldsm_x4(uint32_t addr, uint32_t& r0, uint32_t& r1,
                                        uint32_t& r2, uint32_t& r3) {
    asm volatile("ldmatrix.sync.aligned.m8n8.x4.shared.b16 {%0,%1,%2,%3}, [%4];"
                 : "=r"(r0), "=r"(r1), "=r"(r2), "=r"(r3) : "r"(addr));
}
__device__ __forceinline__ void mma_bf16(float* c, const uint32_t* a, const uint32_t* b) {
    asm volatile("mma.sync.aligned.m16n8k16.row.col.f32.bf16.bf16.f32 "
                 "{%0,%1,%2,%3}, {%4,%5,%6,%7}, {%8,%9}, {%0,%1,%2,%3};"
                 : "+f"(c[0]), "+f"(c[1]), "+f"(c[2]), "+f"(c[3])
                 : "r"(a[0]), "r"(a[1]), "r"(a[2]), "r"(a[3]), "r"(b[0]), "r"(b[1]));
}
__device__ __forceinline__ uint32_t pack_bf16(float a, float b) {
    __nv_bfloat162 h = __floats2bfloat162_rn(a, b);
    return *(uint32_t*)&h;
}
__device__ __forceinline__ uint32_t f2_to_h2(float x, float y) {
    __half2 h = __floats2half2_rn(x, y);
    return *(uint32_t*)&h;
}
__device__ __forceinline__ float4 h4_to_f4(uint2 v) {
    float2 fa = __half22float2(*(__half2*)&v.x);
    float2 fb = __half22float2(*(__half2*)&v.y);
    return make_float4(fa.x, fa.y, fb.x, fb.y);
}

// ---------------------------------------------------------------------------
// CSR build
// ---------------------------------------------------------------------------
__global__ void k_deg(const int* __restrict__ ei, int E) {
    int t = blockIdx.x * blockDim.x + threadIdx.x;
    if (t == 0) g_ctr = 0;
    int e0 = t * 4;
    if (e0 + 4 <= E) {
        int4 d = *(const int4*)(ei + E + e0);
        atomicAdd(&g_deg[d.x], 1);
        atomicAdd(&g_deg[d.y], 1);
        atomicAdd(&g_deg[d.z], 1);
        atomicAdd(&g_deg[d.w], 1);
    } else {
        for (int e = e0; e < E; e++) atomicAdd(&g_deg[ei[E + e]], 1);
    }
}

__global__ void k_offsets(int n) {
    int i = blockIdx.x * blockDim.x + threadIdx.x;
    int lane = threadIdx.x & 31;
    int deg = (i < n) ? g_deg[i] : 0;
    int x = deg;
    #pragma unroll
    for (int o = 1; o < 32; o <<= 1) {
        int y = __shfl_up_sync(0xffffffffu, x, o);
        if (lane >= o) x += y;
    }
    int excl = x - deg;
    int base = 0;
    if (lane == 31) base = atomicAdd(&g_ctr, x);
    base = __shfl_sync(0xffffffffu, base, 31);
    if (i < n) {
        int off = base + excl;
        g_off[i] = off;
        g_cur[i] = off;
        g_dinv[i] = rsqrtf((float)(deg + 1));
    }
}

__global__ void k_fill(const int* __restrict__ ei, int E) {
    int t = blockIdx.x * blockDim.x + threadIdx.x;
    int e0 = t * 4;
    if (e0 + 4 <= E) {
        int4 s = *(const int4*)(ei + e0);
        int4 d = *(const int4*)(ei + E + e0);
        int p0 = atomicAdd(&g_cur[d.x], 1);
        int p1 = atomicAdd(&g_cur[d.y], 1);
        int p2 = atomicAdd(&g_cur[d.z], 1);
        int p3 = atomicAdd(&g_cur[d.w], 1);
        g_csr[p0] = s.x;
        g_csr[p1] = s.y;
        g_csr[p2] = s.z;
        g_csr[p3] = s.w;
    } else {
        for (int e = e0; e < E; e++) {
            int p = atomicAdd(&g_cur[ei[E + e]], 1);
            g_csr[p] = ei[e];
        }
    }
}

// ---------------------------------------------------------------------------
// Weight prep (fused, globals bound in device code)
// ---------------------------------------------------------------------------
__global__ void k_wprep_all(const float* __restrict__ W1, const float* __restrict__ W2) {
    int gi = blockIdx.x * blockDim.x + threadIdx.x;
    const float* W;
    uint32_t *bhi, *blo;
    int i, Nc;
    if (gi < 8192) {
        W = W1; bhi = g_w1hi; blo = g_w1lo; i = gi; Nc = 128;
    } else {
        gi -= 8192;
        if (gi >= 4096) return;
        W = W2; bhi = g_w2hi; blo = g_w2lo; i = gi; Nc = 64;
    }
    int nn = i >> 6;
    int k2 = i & 63;
    int k = k2 << 1;
    float v0 = W[k * Nc + nn];
    float v1 = W[(k + 1) * Nc + nn];
    __nv_bfloat16 h0 = __float2bfloat16(v0);
    __nv_bfloat16 h1 = __float2bfloat16(v1);
    uint32_t hi = (uint32_t)(*(uint16_t*)&h0) | ((uint32_t)(*(uint16_t*)&h1) << 16);
    uint32_t lo = pack_bf16(v0 - __bfloat162float(h0), v1 - __bfloat162float(h1));
    bhi[nn * 64 + k2] = hi;
    blo[nn * 64 + k2] = lo;
}

// ---------------------------------------------------------------------------
// Tensor-core GEMM via mma.sync bf16x3 + ldmatrix (proven)
// MODE 1: A = x (fp32 ext) -> g_h1.  MODE 2: A = g_a1 (fp16) -> g_h2.
// ---------------------------------------------------------------------------
template <int NCOL, int MODE>
__launch_bounds__(256, 1)
__global__ void k_tc_gemm(const float* __restrict__ Aext, int n) {
    constexpr int TR  = 64;
    constexpr int NWM = (NCOL == 128) ? 2 : 4;
    constexpr int MF  = TR / (NWM * 16);
    constexpr int NWN = 8 / NWM;
    constexpr int NF  = NCOL / (NWN * 8);
    constexpr int STR = 272;
    constexpr int A_HI = 0;
    constexpr int A_LO = TR * STR;
    constexpr int B_HI = 2 * TR * STR;
    constexpr int B_LO = B_HI + NCOL * STR;

    extern __shared__ char smraw[];
    char* sm = smraw;
    const uint32_t smb = smem_u32(smraw);

    const int tid  = threadIdx.x;
    const int wid  = tid >> 5;
    const int lane = tid & 31;
    const int row0 = blockIdx.x * TR;

    __half* Od = (MODE == 1) ? g_h1 : g_h2;
    const uint32_t* Bhig = (MODE == 1) ? g_w1hi : g_w2hi;
    const uint32_t* Blog = (MODE == 1) ? g_w1lo : g_w2lo;

    {
        const uint4* bh4 = (const uint4*)Bhig;
        const uint4* bl4 = (const uint4*)Blog;
        constexpr int NB4 = NCOL * 16;
        #pragma unroll
        for (int i = tid; i < NB4; i += 256) {
            int r  = i >> 4;
            int kc = i & 15;
            *(uint4*)(sm + B_HI + r * STR + kc * 16) = bh4[i];
            *(uint4*)(sm + B_LO + r * STR + kc * 16) = bl4[i];
        }
    }

    #pragma unroll
    for (int i = tid; i < TR * 16; i += 256) {
        int r  = i >> 4;
        int kc = i & 15;
        int gr = row0 + r;
        float f[8];
        if (MODE == 1) {
            float4 va = make_float4(0.f, 0.f, 0.f, 0.f);
            float4 vb = make_float4(0.f, 0.f, 0.f, 0.f);
            if (gr < n) {
                va = ((const float4*)Aext)[(size_t)gr * 32 + kc * 2];
                vb = ((const float4*)Aext)[(size_t)gr * 32 + kc * 2 + 1];
            }
            f[0] = va.x; f[1] = va.y; f[2] = va.z; f[3] = va.w;
            f[4] = vb.x; f[5] = vb.y; f[6] = vb.z; f[7] = vb.w;
        } else {
            uint4 v = make_uint4(0u, 0u, 0u, 0u);
            if (gr < n) v = ((const uint4*)g_a1)[(size_t)gr * 16 + kc];
            float2 f0 = __half22float2(*(__half2*)&v.x);
            float2 f1 = __half22float2(*(__half2*)&v.y);
            float2 f2 = __half22float2(*(__half2*)&v.z);
            float2 f3 = __half22float2(*(__half2*)&v.w);
            f[0] = f0.x; f[1] = f0.y; f[2] = f1.x; f[3] = f1.y;
            f[4] = f2.x; f[5] = f2.y; f[6] = f3.x; f[7] = f3.y;
        }
        uint4 hi, lo;
        uint32_t* hp = (uint32_t*)&hi;
        uint32_t* lp = (uint32_t*)&lo;
        #pragma unroll
        for (int j = 0; j < 4; j++) {
            __nv_bfloat162 h = __floats2bfloat162_rn(f[2 * j], f[2 * j + 1]);
            hp[j] = *(uint32_t*)&h;
            lp[j] = pack_bf16(f[2 * j]     - __bfloat162float(h.x),
                              f[2 * j + 1] - __bfloat162float(h.y));
        }
        *(uint4*)(sm + A_HI + r * STR + kc * 16) = hi;
        *(uint4*)(sm + A_LO + r * STR + kc * 16) = lo;
    }
    __syncthreads();

    const int wm   = wid % NWM;
    const int wn   = wid / NWM;
    const int mrow = wm * (MF * 16);
    const int ncol = wn * (NF * 8);
    const int lrow = lane & 7;
    const int sel  = lane >> 3;
    const int gr4  = lane >> 2;
    const int cl2  = (lane & 3) * 2;

    const int arow = mrow + lrow + ((sel & 1) << 3);
    const int akb  = (sel >> 1) << 4;
    const int brow = ncol + lrow + ((sel >> 1) << 3);
    const int bkb  = (sel & 1) << 4;

    float acc[MF][NF][4];
    #pragma unroll
    for (int mf = 0; mf < MF; mf++)
        #pragma unroll
        for (int nf = 0; nf < NF; nf++)
            #pragma unroll
            for (int j = 0; j < 4; j++) acc[mf][nf][j] = 0.f;

    #pragma unroll
    for (int ks = 0; ks < 8; ks++) {
        uint32_t ahi[MF][4], alo[MF][4];
        #pragma unroll
        for (int mf = 0; mf < MF; mf++) {
            uint32_t off = (uint32_t)((arow + mf * 16) * STR + ks * 32 + akb);
            ldsm_x4(smb + A_HI + off, ahi[mf][0], ahi[mf][1], ahi[mf][2], ahi[mf][3]);
            ldsm_x4(smb + A_LO + off, alo[mf][0], alo[mf][1], alo[mf][2], alo[mf][3]);
        }
        uint32_t bhi[NF][2], blo[NF][2];
        #pragma unroll
        for (int nf = 0; nf < NF; nf += 2) {
            uint32_t off = (uint32_t)((brow + nf * 8) * STR + ks * 32 + bkb);
            ldsm_x4(smb + B_HI + off, bhi[nf][0], bhi[nf][1], bhi[nf + 1][0], bhi[nf + 1][1]);
            ldsm_x4(smb + B_LO + off, blo[nf][0], blo[nf][1], blo[nf + 1][0], blo[nf + 1][1]);
        }
        #pragma unroll
        for (int mf = 0; mf < MF; mf++)
            #pragma unroll
            for (int nf = 0; nf < NF; nf++) {
                mma_bf16(acc[mf][nf], ahi[mf], bhi[nf]);
                mma_bf16(acc[mf][nf], ahi[mf], blo[nf]);
                mma_bf16(acc[mf][nf], alo[mf], bhi[nf]);
            }
    }

    #pragma unroll
    for (int mf = 0; mf < MF; mf++) {
        int r0g = row0 + mrow + mf * 16 + gr4;
        int r1g = r0g + 8;
        float dv0 = (r0g < n) ? g_dinv[r0g] : 0.f;
        float dv1 = (r1g < n) ? g_dinv[r1g] : 0.f;
        #pragma unroll
        for (int nf = 0; nf < NF; nf++) {
            int c = ncol + nf * 8 + cl2;
            if (r0g < n) {
                uint32_t p = f2_to_h2(acc[mf][nf][0] * dv0, acc[mf][nf][1] * dv0);
                *(uint32_t*)&Od[(size_t)r0g * NCOL + c] = p;
            }
            if (r1g < n) {
                uint32_t p = f2_to_h2(acc[mf][nf][2] * dv1, acc[mf][nf][3] * dv1);
                *(uint32_t*)&Od[(size_t)r1g * NCOL + c] = p;
            }
        }
    }
}

// ---------------------------------------------------------------------------
// Gather aggregation (CSR, no atomics), fp16 reads, fp32 accumulate
// ---------------------------------------------------------------------------
__global__ void k_gather1(const float* __restrict__ b1, int n) {
    int t = blockIdx.x * blockDim.x + threadIdx.x;
    int lane = t & 31;
    int w = t >> 5;
    if (w >= n) return;
    int st = g_off[w], cnt = g_deg[w];
    const uint2* H = (const uint2*)g_h1;
    float4 acc = h4_to_f4(H[(size_t)w * 32 + lane]);
    int j = 0;
    for (; j + 4 <= cnt; j += 4) {
        int s0 = g_csr[st + j], s1 = g_csr[st + j + 1];
        int s2 = g_csr[st + j + 2], s3 = g_csr[st + j + 3];
        float4 v0 = h4_to_f4(H[(size_t)s0 * 32 + lane]);
        float4 v1 = h4_to_f4(H[(size_t)s1 * 32 + lane]);
        float4 v2 = h4_to_f4(H[(size_t)s2 * 32 + lane]);
        float4 v3 = h4_to_f4(H[(size_t)s3 * 32 + lane]);
        acc.x += (v0.x + v1.x) + (v2.x + v3.x);
        acc.y += (v0.y + v1.y) + (v2.y + v3.y);
        acc.z += (v0.z + v1.z) + (v2.z + v3.z);
        acc.w += (v0.w + v1.w) + (v2.w + v3.w);
    }
    for (; j < cnt; j++) {
        int s = g_csr[st + j];
        float4 v = h4_to_f4(H[(size_t)s * 32 + lane]);
        acc.x += v.x; acc.y += v.y; acc.z += v.z; acc.w += v.w;
    }
    float dv = g_dinv[w];
    float4 b = ((const float4*)b1)[lane];
    float ox = fmaxf(fmaf(acc.x, dv, b.x), 0.f);
    float oy = fmaxf(fmaf(acc.y, dv, b.y), 0.f);
    float oz = fmaxf(fmaf(acc.z, dv, b.z), 0.f);
    float ow = fmaxf(fmaf(acc.w, dv, b.w), 0.f);
    uint2 o;
    o.x = f2_to_h2(ox, oy);
    o.y = f2_to_h2(oz, ow);
    ((uint2*)g_a1)[(size_t)w * 32 + lane] = o;
}

__global__ void k_gather2(float* __restrict__ out, const float* __restrict__ b2, int n) {
    int t = blockIdx.x * blockDim.x + threadIdx.x;
    int ch = t & 15;
    int g = t >> 4;
    if (g >= n) return;
    int st = g_off[g], cnt = g_deg[g];
    const uint2* H = (const uint2*)g_h2;
    float4 acc = h4_to_f4(H[(size_t)g * 16 + ch]);
    int j = 0;
    for (; j + 4 <= cnt; j += 4) {
        int s0 = g_csr[st + j], s1 = g_csr[st + j + 1];
        int s2 = g_csr[st + j + 2], s3 = g_csr[st + j + 3];
        float4 v0 = h4_to_f4(H[(size_t)s0 * 16 + ch]);
        float4 v1 = h4_to_f4(H[(size_t)s1 * 16 + ch]);
        float4 v2 = h4_to_f4(H[(size_t)s2 * 16 + ch]);
        float4 v3 = h4_to_f4(H[(size_t)s3 * 16 + ch]);
        acc.x += (v0.x + v1.x) + (v2.x + v3.x);
        acc.y += (v0.y + v1.y) + (v2.y + v3.y);
        acc.z += (v0.z + v1.z) + (v2.z + v3.z);
        acc.w += (v0.w + v1.w) + (v2.w + v3.w);
    }
    for (; j < cnt; j++) {
        int s = g_csr[st + j];
        float4 v = h4_to_f4(H[(size_t)s * 16 + ch]);
        acc.x += v.x; acc.y += v.y; acc.z += v.z; acc.w += v.w;
    }
    float dv = g_dinv[g];
    float4 b = ((const float4*)b2)[ch];
    acc.x = fmaf(acc.x, dv, b.x);
    acc.y = fmaf(acc.y, dv, b.y);
    acc.z = fmaf(acc.z, dv, b.z);
    acc.w = fmaf(acc.w, dv, b.w);
    ((float4*)out)[(size_t)g * 16 + ch] = acc;
}

// ---------------------------------------------------------------------------
// Launch: deg -> offsets -> fork{ fill (s2) || gemm1 (main) } -> join -> rest
// k_fill (L2-atomic bound) overlaps k_tc_gemm1 (tensor/smem bound).
// ---------------------------------------------------------------------------
extern "C" void kernel_launch(void* const* d_in, const int* in_sizes, int n_in,
                              void* d_out, int out_size) {
    const float* x  = (const float*)d_in[0];
    const int*   ei = (const int*)  d_in[1];
    const float* W1 = (const float*)d_in[2];
    const float* b1 = (const float*)d_in[3];
    const float* W2 = (const float*)d_in[4];
    const float* b2 = (const float*)d_in[5];
    float* out = (float*)d_out;

    const int n = in_sizes[0] / 128;
    const int E = in_sizes[1] / 2;
    const int e4 = (E + 3) / 4;

    const int smem1 = 2 * 64 * 272 + 2 * 128 * 272;  // 104448
    const int smem2 = 2 * 64 * 272 + 2 * 64  * 272;  //  69632
    cudaFuncSetAttribute(k_tc_gemm<128, 1>, cudaFuncAttributeMaxDynamicSharedMemorySize, smem1);
    cudaFuncSetAttribute(k_tc_gemm<64,  2>, cudaFuncAttributeMaxDynamicSharedMemorySize, smem2);

    // Per-call stream/events (leaked deliberately: destroying a forked stream
    // mid-capture invalidates the capture; a few handles over ~5 calls).
    cudaStream_t s2;
    cudaStreamCreateWithFlags(&s2, cudaStreamNonBlocking);
    cudaEvent_t evFork, evJoin;
    cudaEventCreateWithFlags(&evFork, cudaEventDisableTiming);
    cudaEventCreateWithFlags(&evJoin, cudaEventDisableTiming);

    // Weight prep + CSR prefix (all sequential on main stream)
    k_wprep_all<<<48, 256>>>(W1, W2);
    int* degp = nullptr;
    cudaGetSymbolAddress((void**)&degp, g_deg);
    cudaMemsetAsync(degp, 0, n * sizeof(int), 0);
    k_deg<<<(e4 + 255) / 256, 256>>>(ei, E);
    k_offsets<<<(n + 255) / 256, 256>>>(n);

    // Fork: fill on s2, conv1 GEMM on main
    cudaEventRecord(evFork, 0);
    cudaStreamWaitEvent(s2, evFork, 0);
    k_fill<<<(e4 + 255) / 256, 256, 0, s2>>>(ei, E);
    cudaEventRecord(evJoin, s2);

    const int gg = (n + 63) / 64;
    k_tc_gemm<128, 1><<<gg, 256, smem1>>>(x, n);

    // Join: gather1 needs fill + h1
    cudaStreamWaitEvent(0, evJoin, 0);
    k_gather1<<<(n * 32 + 255) / 256, 256>>>(b1, n);

    // conv2
    k_tc_gemm<64, 2><<<gg, 256, smem2>>>(nullptr, n);
    k_gather2<<<(n * 16 + 255) / 256, 256>>>(out, b2, n);
}

// round 14
// speedup vs baseline: 1.1850x; 1.0598x over previous
#include <cuda_runtime.h>
#include <cuda_bf16.h>
#include <cuda_fp16.h>
#include <cstdint>

#define NMAX 100000
#define EMAX 1600000

// ---------------------------------------------------------------------------
// Device scratch (allocation-free rule)
// ---------------------------------------------------------------------------
__device__ int    g_deg [NMAX];
__device__ int    g_off [NMAX];
__device__ int    g_cur [NMAX];
__device__ int    g_ctr;
__device__ int    g_csr [EMAX];
__device__ float  g_dinv[NMAX];
__device__ __align__(16) __half g_h1 [(size_t)NMAX * 128];
__device__ __align__(16) __half g_a1 [(size_t)NMAX * 128];
__device__ __align__(16) __half g_h2 [(size_t)NMAX * 64];
__device__ __align__(16) uint32_t g_w1hi[8192], g_w1lo[8192];
__device__ __align__(16) uint32_t g_w2hi[4096], g_w2lo[4096];

// ---------------------------------------------------------------------------
// Helpers
// ---------------------------------------------------------------------------
__device__ __forceinline__ uint32_t smem_u32(const void* p) {
    uint32_t a;
    asm("{ .reg .u64 t; cvta.to.shared.u64 t, %1; cvt.u32.u64 %0, t; }" : "=r"(a) : "l"(p));
    return a;
}
__device__ __forceinline__ void ldsm_x4(uint32_t addr, uint32_t& r0, uint32_t& r1,
                                        uint32_t& r2, uint32_t& r3) {
    asm volatile("ldmatrix.sync.aligned.m8n8.x4.shared.b16 {%0,%1,%2,%3}, [%4];"
                 : "=r"(r0), "=r"(r1), "=r"(r2), "=r"(r3) : "r"(addr));
}
__device__ __forceinline__ void mma_bf16(float* c, const uint32_t* a, const uint32_t* b) {
    asm volatile("mma.sync.aligned.m16n8k16.row.col.f32.bf16.bf16.f32 "
                 "{%0,%1,%2,%3}, {%4,%5,%6,%7}, {%8,%9}, {%0,%1,%2,%3};"
                 : "+f"(c[0]), "+f"(c[1]), "+f"(c[2]), "+f"(c[3])
                 : "r"(a[0]), "r"(a[1]), "r"(a[2]), "r"(a[3]), "r"(b[0]), "r"(b[1]));
}
__device__ __forceinline__ uint32_t pack_bf16(float a, float b) {
    __nv_bfloat162 h = __floats2bfloat162_rn(a, b);
    return *(uint32_t*)&h;
}
__device__ __forceinline__ uint32_t f2_to_h2(float x, float y) {
    __half2 h = __floats2half2_rn(x, y);
    return *(uint32_t*)&h;
}
__device__ __forceinline__ float4 h4_to_f4(uint2 v) {
    float2 fa = __half22float2(*(__half2*)&v.x);
    float2 fb = __half22float2(*(__half2*)&v.y);
    return make_float4(fa.x, fa.y, fb.x, fb.y);
}
__device__ __forceinline__ void acc_add(float4& a, float4 v) {
    a.x += v.x; a.y += v.y; a.z += v.z; a.w += v.w;
}

// ---------------------------------------------------------------------------
// Fused weight prep + degree histogram: blocks [0,48) do wprep, rest do deg.
// ---------------------------------------------------------------------------
__global__ void k_prep(const float* __restrict__ W1, const float* __restrict__ W2,
                       const int* __restrict__ ei, int E) {
    if (blockIdx.x < 48) {
        int gi = blockIdx.x * blockDim.x + threadIdx.x;
        if (gi == 0) g_ctr = 0;
        const float* W;
        uint32_t *bhi, *blo;
        int i, Nc;
        if (gi < 8192) {
            W = W1; bhi = g_w1hi; blo = g_w1lo; i = gi; Nc = 128;
        } else {
            gi -= 8192;
            if (gi >= 4096) return;
            W = W2; bhi = g_w2hi; blo = g_w2lo; i = gi; Nc = 64;
        }
        int nn = i >> 6;
        int k2 = i & 63;
        int k = k2 << 1;
        float v0 = W[k * Nc + nn];
        float v1 = W[(k + 1) * Nc + nn];
        __nv_bfloat16 h0 = __float2bfloat16(v0);
        __nv_bfloat16 h1 = __float2bfloat16(v1);
        uint32_t hi = (uint32_t)(*(uint16_t*)&h0) | ((uint32_t)(*(uint16_t*)&h1) << 16);
        uint32_t lo = pack_bf16(v0 - __bfloat162float(h0), v1 - __bfloat162float(h1));
        bhi[nn * 64 + k2] = hi;
        blo[nn * 64 + k2] = lo;
    } else {
        int t = (blockIdx.x - 48) * blockDim.x + threadIdx.x;
        int e0 = t * 4;
        if (e0 + 4 <= E) {
            int4 d = *(const int4*)(ei + E + e0);
            atomicAdd(&g_deg[d.x], 1);
            atomicAdd(&g_deg[d.y], 1);
            atomicAdd(&g_deg[d.z], 1);
            atomicAdd(&g_deg[d.w], 1);
        } else {
            for (int e = e0; e < E; e++) atomicAdd(&g_deg[ei[E + e]], 1);
        }
    }
}

__global__ void k_offsets(int n) {
    int i = blockIdx.x * blockDim.x + threadIdx.x;
    int lane = threadIdx.x & 31;
    int deg = (i < n) ? g_deg[i] : 0;
    int x = deg;
    #pragma unroll
    for (int o = 1; o < 32; o <<= 1) {
        int y = __shfl_up_sync(0xffffffffu, x, o);
        if (lane >= o) x += y;
    }
    int excl = x - deg;
    int base = 0;
    if (lane == 31) base = atomicAdd(&g_ctr, x);
    base = __shfl_sync(0xffffffffu, base, 31);
    if (i < n) {
        int off = base + excl;
        g_off[i] = off;
        g_cur[i] = off;
        g_dinv[i] = rsqrtf((float)(deg + 1));
    }
}

__global__ void k_fill(const int* __restrict__ ei, int E) {
    int t = blockIdx.x * blockDim.x + threadIdx.x;
    int e0 = t * 4;
    if (e0 + 4 <= E) {
        int4 s = *(const int4*)(ei + e0);
        int4 d = *(const int4*)(ei + E + e0);
        int p0 = atomicAdd(&g_cur[d.x], 1);
        int p1 = atomicAdd(&g_cur[d.y], 1);
        int p2 = atomicAdd(&g_cur[d.z], 1);
        int p3 = atomicAdd(&g_cur[d.w], 1);
        g_csr[p0] = s.x;
        g_csr[p1] = s.y;
        g_csr[p2] = s.z;
        g_csr[p3] = s.w;
    } else {
        for (int e = e0; e < E; e++) {
            int p = atomicAdd(&g_cur[ei[E + e]], 1);
            g_csr[p] = ei[e];
        }
    }
}

// ---------------------------------------------------------------------------
// Tensor-core GEMM via mma.sync bf16x3 + ldmatrix (proven)
// MODE 1: A = x (fp32 ext) -> g_h1.  MODE 2: A = g_a1 (fp16) -> g_h2.
// ---------------------------------------------------------------------------
template <int NCOL, int MODE>
__launch_bounds__(256, 1)
__global__ void k_tc_gemm(const float* __restrict__ Aext, int n) {
    constexpr int TR  = 64;
    constexpr int NWM = (NCOL == 128) ? 2 : 4;
    constexpr int MF  = TR / (NWM * 16);
    constexpr int NWN = 8 / NWM;
    constexpr int NF  = NCOL / (NWN * 8);
    constexpr int STR = 272;
    constexpr int A_HI = 0;
    constexpr int A_LO = TR * STR;
    constexpr int B_HI = 2 * TR * STR;
    constexpr int B_LO = B_HI + NCOL * STR;

    extern __shared__ char smraw[];
    char* sm = smraw;
    const uint32_t smb = smem_u32(smraw);

    const int tid  = threadIdx.x;
    const int wid  = tid >> 5;
    const int lane = tid & 31;
    const int row0 = blockIdx.x * TR;

    __half* Od = (MODE == 1) ? g_h1 : g_h2;
    const uint32_t* Bhig = (MODE == 1) ? g_w1hi : g_w2hi;
    const uint32_t* Blog = (MODE == 1) ? g_w1lo : g_w2lo;

    {
        const uint4* bh4 = (const uint4*)Bhig;
        const uint4* bl4 = (const uint4*)Blog;
        constexpr int NB4 = NCOL * 16;
        #pragma unroll
        for (int i = tid; i < NB4; i += 256) {
            int r  = i >> 4;
            int kc = i & 15;
            *(uint4*)(sm + B_HI + r * STR + kc * 16) = bh4[i];
            *(uint4*)(sm + B_LO + r * STR + kc * 16) = bl4[i];
        }
    }

    #pragma unroll
    for (int i = tid; i < TR * 16; i += 256) {
        int r  = i >> 4;
        int kc = i & 15;
        int gr = row0 + r;
        float f[8];
        if (MODE == 1) {
            float4 va = make_float4(0.f, 0.f, 0.f, 0.f);
            float4 vb = make_float4(0.f, 0.f, 0.f, 0.f);
            if (gr < n) {
                va = ((const float4*)Aext)[(size_t)gr * 32 + kc * 2];
                vb = ((const float4*)Aext)[(size_t)gr * 32 + kc * 2 + 1];
            }
            f[0] = va.x; f[1] = va.y; f[2] = va.z; f[3] = va.w;
            f[4] = vb.x; f[5] = vb.y; f[6] = vb.z; f[7] = vb.w;
        } else {
            uint4 v = make_uint4(0u, 0u, 0u, 0u);
            if (gr < n) v = ((const uint4*)g_a1)[(size_t)gr * 16 + kc];
            float2 f0 = __half22float2(*(__half2*)&v.x);
            float2 f1 = __half22float2(*(__half2*)&v.y);
            float2 f2 = __half22float2(*(__half2*)&v.z);
            float2 f3 = __half22float2(*(__half2*)&v.w);
            f[0] = f0.x; f[1] = f0.y; f[2] = f1.x; f[3] = f1.y;
            f[4] = f2.x; f[5] = f2.y; f[6] = f3.x; f[7] = f3.y;
        }
        uint4 hi, lo;
        uint32_t* hp = (uint32_t*)&hi;
        uint32_t* lp = (uint32_t*)&lo;
        #pragma unroll
        for (int j = 0; j < 4; j++) {
            __nv_bfloat162 h = __floats2bfloat162_rn(f[2 * j], f[2 * j + 1]);
            hp[j] = *(uint32_t*)&h;
            lp[j] = pack_bf16(f[2 * j]     - __bfloat162float(h.x),
                              f[2 * j + 1] - __bfloat162float(h.y));
        }
        *(uint4*)(sm + A_HI + r * STR + kc * 16) = hi;
        *(uint4*)(sm + A_LO + r * STR + kc * 16) = lo;
    }
    __syncthreads();

    const int wm   = wid % NWM;
    const int wn   = wid / NWM;
    const int mrow = wm * (MF * 16);
    const int ncol = wn * (NF * 8);
    const int lrow = lane & 7;
    const int sel  = lane >> 3;
    const int gr4  = lane >> 2;
    const int cl2  = (lane & 3) * 2;

    const int arow = mrow + lrow + ((sel & 1) << 3);
    const int akb  = (sel >> 1) << 4;
    const int brow = ncol + lrow + ((sel >> 1) << 3);
    const int bkb  = (sel & 1) << 4;

    float acc[MF][NF][4];
    #pragma unroll
    for (int mf = 0; mf < MF; mf++)
        #pragma unroll
        for (int nf = 0; nf < NF; nf++)
            #pragma unroll
            for (int j = 0; j < 4; j++) acc[mf][nf][j] = 0.f;

    #pragma unroll
    for (int ks = 0; ks < 8; ks++) {
        uint32_t ahi[MF][4], alo[MF][4];
        #pragma unroll
        for (int mf = 0; mf < MF; mf++) {
            uint32_t off = (uint32_t)((arow + mf * 16) * STR + ks * 32 + akb);
            ldsm_x4(smb + A_HI + off, ahi[mf][0], ahi[mf][1], ahi[mf][2], ahi[mf][3]);
            ldsm_x4(smb + A_LO + off, alo[mf][0], alo[mf][1], alo[mf][2], alo[mf][3]);
        }
        uint32_t bhi[NF][2], blo[NF][2];
        #pragma unroll
        for (int nf = 0; nf < NF; nf += 2) {
            uint32_t off = (uint32_t)((brow + nf * 8) * STR + ks * 32 + bkb);
            ldsm_x4(smb + B_HI + off, bhi[nf][0], bhi[nf][1], bhi[nf + 1][0], bhi[nf + 1][1]);
            ldsm_x4(smb + B_LO + off, blo[nf][0], blo[nf][1], blo[nf + 1][0], blo[nf + 1][1]);
        }
        #pragma unroll
        for (int mf = 0; mf < MF; mf++)
            #pragma unroll
            for (int nf = 0; nf < NF; nf++) {
                mma_bf16(acc[mf][nf], ahi[mf], bhi[nf]);
                mma_bf16(acc[mf][nf], ahi[mf], blo[nf]);
                mma_bf16(acc[mf][nf], alo[mf], bhi[nf]);
            }
    }

    #pragma unroll
    for (int mf = 0; mf < MF; mf++) {
        int r0g = row0 + mrow + mf * 16 + gr4;
        int r1g = r0g + 8;
        float dv0 = (r0g < n) ? g_dinv[r0g] : 0.f;
        float dv1 = (r1g < n) ? g_dinv[r1g] : 0.f;
        #pragma unroll
        for (int nf = 0; nf < NF; nf++) {
            int c = ncol + nf * 8 + cl2;
            if (r0g < n) {
                uint32_t p = f2_to_h2(acc[mf][nf][0] * dv0, acc[mf][nf][1] * dv0);
                *(uint32_t*)&Od[(size_t)r0g * NCOL + c] = p;
            }
            if (r1g < n) {
                uint32_t p = f2_to_h2(acc[mf][nf][2] * dv1, acc[mf][nf][3] * dv1);
                *(uint32_t*)&Od[(size_t)r1g * NCOL + c] = p;
            }
        }
    }
}

// ---------------------------------------------------------------------------
// Gather aggregation, unroll x8 for MLP=8 on the random L2 loads
// ---------------------------------------------------------------------------
__global__ void k_gather1(const float* __restrict__ b1, int n) {
    int t = blockIdx.x * blockDim.x + threadIdx.x;
    int lane = t & 31;
    int w = t >> 5;
    if (w >= n) return;
    int st = g_off[w], cnt = g_deg[w];
    const uint2* H = (const uint2*)g_h1;
    float4 acc = h4_to_f4(H[(size_t)w * 32 + lane]);
    int j = 0;
    for (; j + 8 <= cnt; j += 8) {
        int s0 = g_csr[st + j],     s1 = g_csr[st + j + 1];
        int s2 = g_csr[st + j + 2], s3 = g_csr[st + j + 3];
        int s4 = g_csr[st + j + 4], s5 = g_csr[st + j + 5];
        int s6 = g_csr[st + j + 6], s7 = g_csr[st + j + 7];
        uint2 r0 = H[(size_t)s0 * 32 + lane];
        uint2 r1 = H[(size_t)s1 * 32 + lane];
        uint2 r2 = H[(size_t)s2 * 32 + lane];
        uint2 r3 = H[(size_t)s3 * 32 + lane];
        uint2 r4 = H[(size_t)s4 * 32 + lane];
        uint2 r5 = H[(size_t)s5 * 32 + lane];
        uint2 r6 = H[(size_t)s6 * 32 + lane];
        uint2 r7 = H[(size_t)s7 * 32 + lane];
        acc_add(acc, h4_to_f4(r0)); acc_add(acc, h4_to_f4(r1));
        acc_add(acc, h4_to_f4(r2)); acc_add(acc, h4_to_f4(r3));
        acc_add(acc, h4_to_f4(r4)); acc_add(acc, h4_to_f4(r5));
        acc_add(acc, h4_to_f4(r6)); acc_add(acc, h4_to_f4(r7));
    }
    for (; j + 4 <= cnt; j += 4) {
        int s0 = g_csr[st + j],     s1 = g_csr[st + j + 1];
        int s2 = g_csr[st + j + 2], s3 = g_csr[st + j + 3];
        uint2 r0 = H[(size_t)s0 * 32 + lane];
        uint2 r1 = H[(size_t)s1 * 32 + lane];
        uint2 r2 = H[(size_t)s2 * 32 + lane];
        uint2 r3 = H[(size_t)s3 * 32 + lane];
        acc_add(acc, h4_to_f4(r0)); acc_add(acc, h4_to_f4(r1));
        acc_add(acc, h4_to_f4(r2)); acc_add(acc, h4_to_f4(r3));
    }
    for (; j < cnt; j++) {
        int s = g_csr[st + j];
        acc_add(acc, h4_to_f4(H[(size_t)s * 32 + lane]));
    }
    float dv = g_dinv[w];
    float4 b = ((const float4*)b1)[lane];
    float ox = fmaxf(fmaf(acc.x, dv, b.x), 0.f);
    float oy = fmaxf(fmaf(acc.y, dv, b.y), 0.f);
    float oz = fmaxf(fmaf(acc.z, dv, b.z), 0.f);
    float ow = fmaxf(fmaf(acc.w, dv, b.w), 0.f);
    uint2 o;
    o.x = f2_to_h2(ox, oy);
    o.y = f2_to_h2(oz, ow);
    ((uint2*)g_a1)[(size_t)w * 32 + lane] = o;
}

__global__ void k_gather2(float* __restrict__ out, const float* __restrict__ b2, int n) {
    int t = blockIdx.x * blockDim.x + threadIdx.x;
    int ch = t & 15;
    int g = t >> 4;
    if (g >= n) return;
    int st = g_off[g], cnt = g_deg[g];
    const uint2* H = (const uint2*)g_h2;
    float4 acc = h4_to_f4(H[(size_t)g * 16 + ch]);
    int j = 0;
    for (; j + 8 <= cnt; j += 8) {
        int s0 = g_csr[st + j],     s1 = g_csr[st + j + 1];
        int s2 = g_csr[st + j + 2], s3 = g_csr[st + j + 3];
        int s4 = g_csr[st + j + 4], s5 = g_csr[st + j + 5];
        int s6 = g_csr[st + j + 6], s7 = g_csr[st + j + 7];
        uint2 r0 = H[(size_t)s0 * 16 + ch];
        uint2 r1 = H[(size_t)s1 * 16 + ch];
        uint2 r2 = H[(size_t)s2 * 16 + ch];
        uint2 r3 = H[(size_t)s3 * 16 + ch];
        uint2 r4 = H[(size_t)s4 * 16 + ch];
        uint2 r5 = H[(size_t)s5 * 16 + ch];
        uint2 r6 = H[(size_t)s6 * 16 + ch];
        uint2 r7 = H[(size_t)s7 * 16 + ch];
        acc_add(acc, h4_to_f4(r0)); acc_add(acc, h4_to_f4(r1));
        acc_add(acc, h4_to_f4(r2)); acc_add(acc, h4_to_f4(r3));
        acc_add(acc, h4_to_f4(r4)); acc_add(acc, h4_to_f4(r5));
        acc_add(acc, h4_to_f4(r6)); acc_add(acc, h4_to_f4(r7));
    }
    for (; j + 4 <= cnt; j += 4) {
        int s0 = g_csr[st + j],     s1 = g_csr[st + j + 1];
        int s2 = g_csr[st + j + 2], s3 = g_csr[st + j + 3];
        uint2 r0 = H[(size_t)s0 * 16 + ch];
        uint2 r1 = H[(size_t)s1 * 16 + ch];
        uint2 r2 = H[(size_t)s2 * 16 + ch];
        uint2 r3 = H[(size_t)s3 * 16 + ch];
        acc_add(acc, h4_to_f4(r0)); acc_add(acc, h4_to_f4(r1));
        acc_add(acc, h4_to_f4(r2)); acc_add(acc, h4_to_f4(r3));
    }
    for (; j < cnt; j++) {
        int s = g_csr[st + j];
        acc_add(acc, h4_to_f4(H[(size_t)s * 16 + ch]));
    }
    float dv = g_dinv[g];
    float4 b = ((const float4*)b2)[ch];
    acc.x = fmaf(acc.x, dv, b.x);
    acc.y = fmaf(acc.y, dv, b.y);
    acc.z = fmaf(acc.z, dv, b.z);
    acc.w = fmaf(acc.w, dv, b.w);
    ((float4*)out)[(size_t)g * 16 + ch] = acc;
}

// ---------------------------------------------------------------------------
// Launch: prep(wprep+deg fused) -> offsets -> fork{ fill || gemm1 } -> join
// ---------------------------------------------------------------------------
extern "C" void kernel_launch(void* const* d_in, const int* in_sizes, int n_in,
                              void* d_out, int out_size) {
    const float* x  = (const float*)d_in[0];
    const int*   ei = (const int*)  d_in[1];
    const float* W1 = (const float*)d_in[2];
    const float* b1 = (const float*)d_in[3];
    const float* W2 = (const float*)d_in[4];
    const float* b2 = (const float*)d_in[5];
    float* out = (float*)d_out;

    const int n = in_sizes[0] / 128;
    const int E = in_sizes[1] / 2;
    const int e4 = (E + 3) / 4;

    const int smem1 = 2 * 64 * 272 + 2 * 128 * 272;  // 104448
    const int smem2 = 2 * 64 * 272 + 2 * 64  * 272;  //  69632
    cudaFuncSetAttribute(k_tc_gemm<128, 1>, cudaFuncAttributeMaxDynamicSharedMemorySize, smem1);
    cudaFuncSetAttribute(k_tc_gemm<64,  2>, cudaFuncAttributeMaxDynamicSharedMemorySize, smem2);

    // Per-call stream/events (leaked deliberately; graph-capture safe)
    cudaStream_t s2;
    cudaStreamCreateWithFlags(&s2, cudaStreamNonBlocking);
    cudaEvent_t evFork, evJoin;
    cudaEventCreateWithFlags(&evFork, cudaEventDisableTiming);
    cudaEventCreateWithFlags(&evJoin, cudaEventDisableTiming);

    // memset deg, then fused wprep+deg, then offsets
    int* degp = nullptr;
    cudaGetSymbolAddress((void**)&degp, g_deg);
    cudaMemsetAsync(degp, 0, n * sizeof(int), 0);
    k_prep<<<48 + (e4 + 255) / 256, 256>>>(W1, W2, ei, E);
    k_offsets<<<(n + 255) / 256, 256>>>(n);

    // Fork: fill on s2, conv1 GEMM on main
    cudaEventRecord(evFork, 0);
    cudaStreamWaitEvent(s2, evFork, 0);
    k_fill<<<(e4 + 255) / 256, 256, 0, s2>>>(ei, E);
    cudaEventRecord(evJoin, s2);

    const int gg = (n + 63) / 64;
    k_tc_gemm<128, 1><<<gg, 256, smem1>>>(x, n);

    // Join: gather1 needs fill + h1
    cudaStreamWaitEvent(0, evJoin, 0);
    k_gather1<<<(n * 32 + 255) / 256, 256>>>(b1, n);

    // conv2
    k_tc_gemm<64, 2><<<gg, 256, smem2>>>(nullptr, n);
    k_gather2<<<(n * 16 + 255) / 256, 256>>>(out, b2, n);
}

// round 15
// speedup vs baseline: 1.2147x; 1.0251x over previous
#include <cuda_runtime.h>
#include <cuda_bf16.h>
#include <cuda_fp16.h>
#include <cstdint>

#define NMAX 100000
#define EMAX 1600000

// ---------------------------------------------------------------------------
// Device scratch (allocation-free rule)
// ---------------------------------------------------------------------------
__device__ int    g_deg [NMAX];
__device__ int    g_off [NMAX];
__device__ int    g_cur [NMAX];
__device__ int    g_ctr;
__device__ int    g_csr [EMAX];
__device__ float  g_dinv[NMAX];
__device__ __align__(16) __half g_h1 [(size_t)NMAX * 128];
__device__ __align__(16) __half g_a1 [(size_t)NMAX * 128];
__device__ __align__(16) __half g_h2 [(size_t)NMAX * 64];
__device__ __align__(16) uint32_t g_w1hi[8192], g_w1lo[8192];
__device__ __align__(16) uint32_t g_w2hi[4096], g_w2lo[4096];

// ---------------------------------------------------------------------------
// Helpers
// ---------------------------------------------------------------------------
__device__ __forceinline__ uint32_t smem_u32(const void* p) {
    uint32_t a;
    asm("{ .reg .u64 t; cvta.to.shared.u64 t, %1; cvt.u32.u64 %0, t; }" : "=r"(a) : "l"(p));
    return a;
}
__device__ __forceinline__ void ldsm_x4(uint32_t addr, uint32_t& r0, uint32_t& r1,
                                        uint32_t& r2, uint32_t& r3) {
    asm volatile("ldmatrix.sync.aligned.m8n8.x4.shared.b16 {%0,%1,%2,%3}, [%4];"
                 : "=r"(r0), "=r"(r1), "=r"(r2), "=r"(r3) : "r"(addr));
}
__device__ __forceinline__ void mma_bf16(float* c, const uint32_t* a, const uint32_t* b) {
    asm volatile("mma.sync.aligned.m16n8k16.row.col.f32.bf16.bf16.f32 "
                 "{%0,%1,%2,%3}, {%4,%5,%6,%7}, {%8,%9}, {%0,%1,%2,%3};"
                 : "+f"(c[0]), "+f"(c[1]), "+f"(c[2]), "+f"(c[3])
                 : "r"(a[0]), "r"(a[1]), "r"(a[2]), "r"(a[3]), "r"(b[0]), "r"(b[1]));
}
__device__ __forceinline__ uint32_t pack_bf16(float a, float b) {
    __nv_bfloat162 h = __floats2bfloat162_rn(a, b);
    return *(uint32_t*)&h;
}
__device__ __forceinline__ uint32_t f2_to_h2(float x, float y) {
    __half2 h = __floats2half2_rn(x, y);
    return *(uint32_t*)&h;
}
__device__ __forceinline__ float4 h4_to_f4(uint2 v) {
    float2 fa = __half22float2(*(__half2*)&v.x);
    float2 fb = __half22float2(*(__half2*)&v.y);
    return make_float4(fa.x, fa.y, fb.x, fb.y);
}
__device__ __forceinline__ void acc_add(float4& a, float4 v) {
    a.x += v.x; a.y += v.y; a.z += v.z; a.w += v.w;
}

// ---------------------------------------------------------------------------
// Fused weight prep + degree histogram: blocks [0,48) do wprep, rest do deg.
// ---------------------------------------------------------------------------
__global__ void k_prep(const float* __restrict__ W1, const float* __restrict__ W2,
                       const int* __restrict__ ei, int E) {
    if (blockIdx.x < 48) {
        int gi = blockIdx.x * blockDim.x + threadIdx.x;
        if (gi == 0) g_ctr = 0;
        const float* W;
        uint32_t *bhi, *blo;
        int i, Nc;
        if (gi < 8192) {
            W = W1; bhi = g_w1hi; blo = g_w1lo; i = gi; Nc = 128;
        } else {
            gi -= 8192;
            if (gi >= 4096) return;
            W = W2; bhi = g_w2hi; blo = g_w2lo; i = gi; Nc = 64;
        }
        int nn = i >> 6;
        int k2 = i & 63;
        int k = k2 << 1;
        float v0 = W[k * Nc + nn];
        float v1 = W[(k + 1) * Nc + nn];
        __nv_bfloat16 h0 = __float2bfloat16(v0);
        __nv_bfloat16 h1 = __float2bfloat16(v1);
        uint32_t hi = (uint32_t)(*(uint16_t*)&h0) | ((uint32_t)(*(uint16_t*)&h1) << 16);
        uint32_t lo = pack_bf16(v0 - __bfloat162float(h0), v1 - __bfloat162float(h1));
        bhi[nn * 64 + k2] = hi;
        blo[nn * 64 + k2] = lo;
    } else {
        int t = (blockIdx.x - 48) * blockDim.x + threadIdx.x;
        int e0 = t * 4;
        if (e0 + 4 <= E) {
            int4 d = *(const int4*)(ei + E + e0);
            atomicAdd(&g_deg[d.x], 1);
            atomicAdd(&g_deg[d.y], 1);
            atomicAdd(&g_deg[d.z], 1);
            atomicAdd(&g_deg[d.w], 1);
        } else {
            for (int e = e0; e < E; e++) atomicAdd(&g_deg[ei[E + e]], 1);
        }
    }
}

__global__ void k_offsets(int n) {
    int i = blockIdx.x * blockDim.x + threadIdx.x;
    int lane = threadIdx.x & 31;
    int deg = (i < n) ? g_deg[i] : 0;
    int x = deg;
    #pragma unroll
    for (int o = 1; o < 32; o <<= 1) {
        int y = __shfl_up_sync(0xffffffffu, x, o);
        if (lane >= o) x += y;
    }
    int excl = x - deg;
    int base = 0;
    if (lane == 31) base = atomicAdd(&g_ctr, x);
    base = __shfl_sync(0xffffffffu, base, 31);
    if (i < n) {
        int off = base + excl;
        g_off[i] = off;
        g_cur[i] = off;
        g_dinv[i] = rsqrtf((float)(deg + 1));
    }
}

__global__ void k_fill(const int* __restrict__ ei, int E) {
    int t = blockIdx.x * blockDim.x + threadIdx.x;
    int e0 = t * 4;
    if (e0 + 4 <= E) {
        int4 s = *(const int4*)(ei + e0);
        int4 d = *(const int4*)(ei + E + e0);
        int p0 = atomicAdd(&g_cur[d.x], 1);
        int p1 = atomicAdd(&g_cur[d.y], 1);
        int p2 = atomicAdd(&g_cur[d.z], 1);
        int p3 = atomicAdd(&g_cur[d.w], 1);
        g_csr[p0] = s.x;
        g_csr[p1] = s.y;
        g_csr[p2] = s.z;
        g_csr[p3] = s.w;
    } else {
        for (int e = e0; e < E; e++) {
            int p = atomicAdd(&g_cur[ei[E + e]], 1);
            g_csr[p] = ei[e];
        }
    }
}

// ---------------------------------------------------------------------------
// Tensor-core GEMM via mma.sync bf16x3 + ldmatrix.
// R15: __launch_bounds__(256, 2) -> regs capped at 128, 2 CTAs/SM
// (2 x 104448B smem = 209KB <= 228KB carveout) to double latency hiding.
// MODE 1: A = x (fp32 ext) -> g_h1.  MODE 2: A = g_a1 (fp16) -> g_h2.
// ---------------------------------------------------------------------------
template <int NCOL, int MODE>
__launch_bounds__(256, 2)
__global__ void k_tc_gemm(const float* __restrict__ Aext, int n) {
    constexpr int TR  = 64;
    constexpr int NWM = (NCOL == 128) ? 2 : 4;
    constexpr int MF  = TR / (NWM * 16);
    constexpr int NWN = 8 / NWM;
    constexpr int NF  = NCOL / (NWN * 8);
    constexpr int STR = 272;
    constexpr int A_HI = 0;
    constexpr int A_LO = TR * STR;
    constexpr int B_HI = 2 * TR * STR;
    constexpr int B_LO = B_HI + NCOL * STR;

    extern __shared__ char smraw[];
    char* sm = smraw;
    const uint32_t smb = smem_u32(smraw);

    const int tid  = threadIdx.x;
    const int wid  = tid >> 5;
    const int lane = tid & 31;
    const int row0 = blockIdx.x * TR;

    __half* Od = (MODE == 1) ? g_h1 : g_h2;
    const uint32_t* Bhig = (MODE == 1) ? g_w1hi : g_w2hi;
    const uint32_t* Blog = (MODE == 1) ? g_w1lo : g_w2lo;

    {
        const uint4* bh4 = (const uint4*)Bhig;
        const uint4* bl4 = (const uint4*)Blog;
        constexpr int NB4 = NCOL * 16;
        #pragma unroll
        for (int i = tid; i < NB4; i += 256) {
            int r  = i >> 4;
            int kc = i & 15;
            *(uint4*)(sm + B_HI + r * STR + kc * 16) = bh4[i];
            *(uint4*)(sm + B_LO + r * STR + kc * 16) = bl4[i];
        }
    }

    #pragma unroll
    for (int i = tid; i < TR * 16; i += 256) {
        int r  = i >> 4;
        int kc = i & 15;
        int gr = row0 + r;
        float f[8];
        if (MODE == 1) {
            float4 va = make_float4(0.f, 0.f, 0.f, 0.f);
            float4 vb = make_float4(0.f, 0.f, 0.f, 0.f);
            if (gr < n) {
                va = ((const float4*)Aext)[(size_t)gr * 32 + kc * 2];
                vb = ((const float4*)Aext)[(size_t)gr * 32 + kc * 2 + 1];
            }
            f[0] = va.x; f[1] = va.y; f[2] = va.z; f[3] = va.w;
            f[4] = vb.x; f[5] = vb.y; f[6] = vb.z; f[7] = vb.w;
        } else {
            uint4 v = make_uint4(0u, 0u, 0u, 0u);
            if (gr < n) v = ((const uint4*)g_a1)[(size_t)gr * 16 + kc];
            float2 f0 = __half22float2(*(__half2*)&v.x);
            float2 f1 = __half22float2(*(__half2*)&v.y);
            float2 f2 = __half22float2(*(__half2*)&v.z);
            float2 f3 = __half22float2(*(__half2*)&v.w);
            f[0] = f0.x; f[1] = f0.y; f[2] = f1.x; f[3] = f1.y;
            f[4] = f2.x; f[5] = f2.y; f[6] = f3.x; f[7] = f3.y;
        }
        uint4 hi, lo;
        uint32_t* hp = (uint32_t*)&hi;
        uint32_t* lp = (uint32_t*)&lo;
        #pragma unroll
        for (int j = 0; j < 4; j++) {
            __nv_bfloat162 h = __floats2bfloat162_rn(f[2 * j], f[2 * j + 1]);
            hp[j] = *(uint32_t*)&h;
            lp[j] = pack_bf16(f[2 * j]     - __bfloat162float(h.x),
                              f[2 * j + 1] - __bfloat162float(h.y));
        }
        *(uint4*)(sm + A_HI + r * STR + kc * 16) = hi;
        *(uint4*)(sm + A_LO + r * STR + kc * 16) = lo;
    }
    __syncthreads();

    const int wm   = wid % NWM;
    const int wn   = wid / NWM;
    const int mrow = wm * (MF * 16);
    const int ncol = wn * (NF * 8);
    const int lrow = lane & 7;
    const int sel  = lane >> 3;
    const int gr4  = lane >> 2;
    const int cl2  = (lane & 3) * 2;

    const int arow = mrow + lrow + ((sel & 1) << 3);
    const int akb  = (sel >> 1) << 4;
    const int brow = ncol + lrow + ((sel >> 1) << 3);
    const int bkb  = (sel & 1) << 4;

    float acc[MF][NF][4];
    #pragma unroll
    for (int mf = 0; mf < MF; mf++)
        #pragma unroll
        for (int nf = 0; nf < NF; nf++)
            #pragma unroll
            for (int j = 0; j < 4; j++) acc[mf][nf][j] = 0.f;

    #pragma unroll
    for (int ks = 0; ks < 8; ks++) {
        uint32_t ahi[MF][4], alo[MF][4];
        #pragma unroll
        for (int mf = 0; mf < MF; mf++) {
            uint32_t off = (uint32_t)((arow + mf * 16) * STR + ks * 32 + akb);
            ldsm_x4(smb + A_HI + off, ahi[mf][0], ahi[mf][1], ahi[mf][2], ahi[mf][3]);
            ldsm_x4(smb + A_LO + off, alo[mf][0], alo[mf][1], alo[mf][2], alo[mf][3]);
        }
        uint32_t bhi[NF][2], blo[NF][2];
        #pragma unroll
        for (int nf = 0; nf < NF; nf += 2) {
            uint32_t off = (uint32_t)((brow + nf * 8) * STR + ks * 32 + bkb);
            ldsm_x4(smb + B_HI + off, bhi[nf][0], bhi[nf][1], bhi[nf + 1][0], bhi[nf + 1][1]);
            ldsm_x4(smb + B_LO + off, blo[nf][0], blo[nf][1], blo[nf + 1][0], blo[nf + 1][1]);
        }
        #pragma unroll
        for (int mf = 0; mf < MF; mf++)
            #pragma unroll
            for (int nf = 0; nf < NF; nf++) {
                mma_bf16(acc[mf][nf], ahi[mf], bhi[nf]);
                mma_bf16(acc[mf][nf], ahi[mf], blo[nf]);
                mma_bf16(acc[mf][nf], alo[mf], bhi[nf]);
            }
    }

    #pragma unroll
    for (int mf = 0; mf < MF; mf++) {
        int r0g = row0 + mrow + mf * 16 + gr4;
        int r1g = r0g + 8;
        float dv0 = (r0g < n) ? g_dinv[r0g] : 0.f;
        float dv1 = (r1g < n) ? g_dinv[r1g] : 0.f;
        #pragma unroll
        for (int nf = 0; nf < NF; nf++) {
            int c = ncol + nf * 8 + cl2;
            if (r0g < n) {
                uint32_t p = f2_to_h2(acc[mf][nf][0] * dv0, acc[mf][nf][1] * dv0);
                *(uint32_t*)&Od[(size_t)r0g * NCOL + c] = p;
            }
            if (r1g < n) {
                uint32_t p = f2_to_h2(acc[mf][nf][2] * dv1, acc[mf][nf][3] * dv1);
                *(uint32_t*)&Od[(size_t)r1g * NCOL + c] = p;
            }
        }
    }
}

// ---------------------------------------------------------------------------
// Gather aggregation, unroll x8 for MLP=8 on the random L2 loads
// ---------------------------------------------------------------------------
__global__ void k_gather1(const float* __restrict__ b1, int n) {
    int t = blockIdx.x * blockDim.x + threadIdx.x;
    int lane = t & 31;
    int w = t >> 5;
    if (w >= n) return;
    int st = g_off[w], cnt = g_deg[w];
    const uint2* H = (const uint2*)g_h1;
    float4 acc = h4_to_f4(H[(size_t)w * 32 + lane]);
    int j = 0;
    for (; j + 8 <= cnt; j += 8) {
        int s0 = g_csr[st + j],     s1 = g_csr[st + j + 1];
        int s2 = g_csr[st + j + 2], s3 = g_csr[st + j + 3];
        int s4 = g_csr[st + j + 4], s5 = g_csr[st + j + 5];
        int s6 = g_csr[st + j + 6], s7 = g_csr[st + j + 7];
        uint2 r0 = H[(size_t)s0 * 32 + lane];
        uint2 r1 = H[(size_t)s1 * 32 + lane];
        uint2 r2 = H[(size_t)s2 * 32 + lane];
        uint2 r3 = H[(size_t)s3 * 32 + lane];
        uint2 r4 = H[(size_t)s4 * 32 + lane];
        uint2 r5 = H[(size_t)s5 * 32 + lane];
        uint2 r6 = H[(size_t)s6 * 32 + lane];
        uint2 r7 = H[(size_t)s7 * 32 + lane];
        acc_add(acc, h4_to_f4(r0)); acc_add(acc, h4_to_f4(r1));
        acc_add(acc, h4_to_f4(r2)); acc_add(acc, h4_to_f4(r3));
        acc_add(acc, h4_to_f4(r4)); acc_add(acc, h4_to_f4(r5));
        acc_add(acc, h4_to_f4(r6)); acc_add(acc, h4_to_f4(r7));
    }
    for (; j + 4 <= cnt; j += 4) {
        int s0 = g_csr[st + j],     s1 = g_csr[st + j + 1];
        int s2 = g_csr[st + j + 2], s3 = g_csr[st + j + 3];
        uint2 r0 = H[(size_t)s0 * 32 + lane];
        uint2 r1 = H[(size_t)s1 * 32 + lane];
        uint2 r2 = H[(size_t)s2 * 32 + lane];
        uint2 r3 = H[(size_t)s3 * 32 + lane];
        acc_add(acc, h4_to_f4(r0)); acc_add(acc, h4_to_f4(r1));
        acc_add(acc, h4_to_f4(r2)); acc_add(acc, h4_to_f4(r3));
    }
    for (; j < cnt; j++) {
        int s = g_csr[st + j];
        acc_add(acc, h4_to_f4(H[(size_t)s * 32 + lane]));
    }
    float dv = g_dinv[w];
    float4 b = ((const float4*)b1)[lane];
    float ox = fmaxf(fmaf(acc.x, dv, b.x), 0.f);
    float oy = fmaxf(fmaf(acc.y, dv, b.y), 0.f);
    float oz = fmaxf(fmaf(acc.z, dv, b.z), 0.f);
    float ow = fmaxf(fmaf(acc.w, dv, b.w), 0.f);
    uint2 o;
    o.x = f2_to_h2(ox, oy);
    o.y = f2_to_h2(oz, ow);
    ((uint2*)g_a1)[(size_t)w * 32 + lane] = o;
}

__global__ void k_gather2(float* __restrict__ out, const float* __restrict__ b2, int n) {
    int t = blockIdx.x * blockDim.x + threadIdx.x;
    int ch = t & 15;
    int g = t >> 4;
    if (g >= n) return;
    int st = g_off[g], cnt = g_deg[g];
    const uint2* H = (const uint2*)g_h2;
    float4 acc = h4_to_f4(H[(size_t)g * 16 + ch]);
    int j = 0;
    for (; j + 8 <= cnt; j += 8) {
        int s0 = g_csr[st + j],     s1 = g_csr[st + j + 1];
        int s2 = g_csr[st + j + 2], s3 = g_csr[st + j + 3];
        int s4 = g_csr[st + j + 4], s5 = g_csr[st + j + 5];
        int s6 = g_csr[st + j + 6], s7 = g_csr[st + j + 7];
        uint2 r0 = H[(size_t)s0 * 16 + ch];
        uint2 r1 = H[(size_t)s1 * 16 + ch];
        uint2 r2 = H[(size_t)s2 * 16 + ch];
        uint2 r3 = H[(size_t)s3 * 16 + ch];
        uint2 r4 = H[(size_t)s4 * 16 + ch];
        uint2 r5 = H[(size_t)s5 * 16 + ch];
        uint2 r6 = H[(size_t)s6 * 16 + ch];
        uint2 r7 = H[(size_t)s7 * 16 + ch];
        acc_add(acc, h4_to_f4(r0)); acc_add(acc, h4_to_f4(r1));
        acc_add(acc, h4_to_f4(r2)); acc_add(acc, h4_to_f4(r3));
        acc_add(acc, h4_to_f4(r4)); acc_add(acc, h4_to_f4(r5));
        acc_add(acc, h4_to_f4(r6)); acc_add(acc, h4_to_f4(r7));
    }
    for (; j + 4 <= cnt; j += 4) {
        int s0 = g_csr[st + j],     s1 = g_csr[st + j + 1];
        int s2 = g_csr[st + j + 2], s3 = g_csr[st + j + 3];
        uint2 r0 = H[(size_t)s0 * 16 + ch];
        uint2 r1 = H[(size_t)s1 * 16 + ch];
        uint2 r2 = H[(size_t)s2 * 16 + ch];
        uint2 r3 = H[(size_t)s3 * 16 + ch];
        acc_add(acc, h4_to_f4(r0)); acc_add(acc, h4_to_f4(r1));
        acc_add(acc, h4_to_f4(r2)); acc_add(acc, h4_to_f4(r3));
    }
    for (; j < cnt; j++) {
        int s = g_csr[st + j];
        acc_add(acc, h4_to_f4(H[(size_t)s * 16 + ch]));
    }
    float dv = g_dinv[g];
    float4 b = ((const float4*)b2)[ch];
    acc.x = fmaf(acc.x, dv, b.x);
    acc.y = fmaf(acc.y, dv, b.y);
    acc.z = fmaf(acc.z, dv, b.z);
    acc.w = fmaf(acc.w, dv, b.w);
    ((float4*)out)[(size_t)g * 16 + ch] = acc;
}

// ---------------------------------------------------------------------------
// Launch: prep(wprep+deg fused) -> offsets -> fork{ fill || gemm1 } -> join
// ---------------------------------------------------------------------------
extern "C" void kernel_launch(void* const* d_in, const int* in_sizes, int n_in,
                              void* d_out, int out_size) {
    const float* x  = (const float*)d_in[0];
    const int*   ei = (const int*)  d_in[1];
    const float* W1 = (const float*)d_in[2];
    const float* b1 = (const float*)d_in[3];
    const float* W2 = (const float*)d_in[4];
    const float* b2 = (const float*)d_in[5];
    float* out = (float*)d_out;

    const int n = in_sizes[0] / 128;
    const int E = in_sizes[1] / 2;
    const int e4 = (E + 3) / 4;

    const int smem1 = 2 * 64 * 272 + 2 * 128 * 272;  // 104448
    const int smem2 = 2 * 64 * 272 + 2 * 64  * 272;  //  69632
    cudaFuncSetAttribute(k_tc_gemm<128, 1>, cudaFuncAttributeMaxDynamicSharedMemorySize, smem1);
    cudaFuncSetAttribute(k_tc_gemm<64,  2>, cudaFuncAttributeMaxDynamicSharedMemorySize, smem2);

    // Per-call stream/events (leaked deliberately; graph-capture safe)
    cudaStream_t s2;
    cudaStreamCreateWithFlags(&s2, cudaStreamNonBlocking);
    cudaEvent_t evFork, evJoin;
    cudaEventCreateWithFlags(&evFork, cudaEventDisableTiming);
    cudaEventCreateWithFlags(&evJoin, cudaEventDisableTiming);

    // memset deg, then fused wprep+deg, then offsets
    int* degp = nullptr;
    cudaGetSymbolAddress((void**)&degp, g_deg);
    cudaMemsetAsync(degp, 0, n * sizeof(int), 0);
    k_prep<<<48 + (e4 + 255) / 256, 256>>>(W1, W2, ei, E);
    k_offsets<<<(n + 255) / 256, 256>>>(n);

    // Fork: fill on s2, conv1 GEMM on main
    cudaEventRecord(evFork, 0);
    cudaStreamWaitEvent(s2, evFork, 0);
    k_fill<<<(e4 + 255) / 256, 256, 0, s2>>>(ei, E);
    cudaEventRecord(evJoin, s2);

    const int gg = (n + 63) / 64;
    k_tc_gemm<128, 1><<<gg, 256, smem1>>>(x, n);

    // Join: gather1 needs fill + h1
    cudaStreamWaitEvent(0, evJoin, 0);
    k_gather1<<<(n * 32 + 255) / 256, 256>>>(b1, n);

    // conv2
    k_tc_gemm<64, 2><<<gg, 256, smem2>>>(nullptr, n);
    k_gather2<<<(n * 16 + 255) / 256, 256>>>(out, b2, n);
}